// round 5
// baseline (speedup 1.0000x reference)
#include <cuda_runtime.h>
#include <stdint.h>

#define NN   20000
#define FIN  8710
#define HID  128
#define NC   70
#define NE   640000

// ---------------- scratch (static device globals; no runtime alloc) -------------
__device__ float d_H1[NN * HID];      // x @ W1
__device__ float d_G1[NN * HID];      // relu(Â H1 + b1)
__device__ float d_H2[NN * NC];       // G1 @ W2
__device__ int   d_deg[NN];
__device__ float d_dinv[NN];
__device__ int   d_rowptr[NN + 1];
__device__ int   d_pos[NN];
__device__ int   d_col[NE];

// ---------------- degree / CSR build --------------------------------------------
__global__ void k_init_deg() {
    int i = blockIdx.x * blockDim.x + threadIdx.x;
    if (i < NN) d_deg[i] = 1;                       // self-loop
}

__global__ void k_count(const int* __restrict__ dst) {
    int e = blockIdx.x * blockDim.x + threadIdx.x;
    if (e < NE) atomicAdd(&d_deg[dst[e]], 1);
}

__global__ void k_dinv() {
    int i = blockIdx.x * blockDim.x + threadIdx.x;
    if (i < NN) d_dinv[i] = rsqrtf((float)d_deg[i]);
}

// single-block exclusive scan of (deg-1) -> rowptr, also seeds pos[]
__global__ void k_scan() {
    __shared__ int sm[1024];
    __shared__ int carry;
    int t = threadIdx.x;
    if (t == 0) carry = 0;
    __syncthreads();
    for (int base = 0; base < NN; base += 1024) {
        int i = base + t;
        int v = (i < NN) ? (d_deg[i] - 1) : 0;
        sm[t] = v;
        __syncthreads();
        for (int off = 1; off < 1024; off <<= 1) {
            int a = (t >= off) ? sm[t - off] : 0;
            __syncthreads();
            sm[t] += a;
            __syncthreads();
        }
        if (i < NN) {
            int ex = carry + sm[t] - v;
            d_rowptr[i] = ex;
            d_pos[i]    = ex;
        }
        __syncthreads();
        if (t == 1023) carry += sm[1023];
        __syncthreads();
    }
    if (t == 0) d_rowptr[NN] = carry;
}

__global__ void k_fill(const int* __restrict__ src, const int* __restrict__ dst) {
    int e = blockIdx.x * blockDim.x + threadIdx.x;
    if (e < NE) {
        int d    = dst[e];
        int slot = atomicAdd(&d_pos[d], 1);
        d_col[slot] = src[e];
    }
}

// sort each row's src indices -> deterministic fp32 summation order every call
__global__ void k_sort() {
    int v = blockIdx.x * blockDim.x + threadIdx.x;
    if (v >= NN) return;
    int b = d_rowptr[v], e = d_rowptr[v + 1];
    for (int i = b + 1; i < e; i++) {
        int key = d_col[i];
        int j = i - 1;
        while (j >= b && d_col[j] > key) { d_col[j + 1] = d_col[j]; j--; }
        d_col[j + 1] = key;
    }
}

// ---------------- GEMM1: H1[N=20000,128] = X[N,8710] @ W1[8710,128] -------------
// packed fp32 (fma.rn.f32x2) microkernel; BM=32, BN=128, BK=16, 128 threads,
// thread tile 4M x 8N with M-paired 64-bit accumulators.

__device__ __forceinline__ unsigned long long pk2(float x) {
    unsigned long long r;
    asm("mov.b64 %0, {%1, %1};" : "=l"(r) : "f"(x));
    return r;
}
__device__ __forceinline__ void fma2(unsigned long long& d,
                                     unsigned long long a, unsigned long long b) {
    asm("fma.rn.f32x2 %0, %1, %2, %0;" : "+l"(d) : "l"(a), "l"(b));
}

#define BM 32
#define BK 16

__global__ void __launch_bounds__(128) k_gemm1(const float* __restrict__ X,
                                               const float* __restrict__ W) {
    __shared__ float As[2][BK * BM];    // transposed: As[k][m]
    __shared__ float Bs[2][BK * HID];   // Bs[k][n]

    const int t  = threadIdx.x;
    const int tm = t >> 4;              // 0..7  (M group of 4)
    const int tn = t & 15;              // 0..15 (N group of 8)
    const int bm = blockIdx.x * BM;

    // A global-load mapping: 32 rows x 16 k, 4 floats/thread (2 float2)
    const int la_row = t >> 2;          // 0..31
    const int la_k   = (t & 3) * 4;     // 0,4,8,12
    const float* Xp = X + (long)(bm + la_row) * FIN + la_k;

    // B global-load mapping: interleaved float4s -> conflict-free STS.128
    const int lane = t & 31;
    const int wrp  = t >> 5;            // 0..3

    unsigned long long acc[2][8];
#pragma unroll
    for (int p = 0; p < 2; p++)
#pragma unroll
        for (int j = 0; j < 8; j++) acc[p][j] = 0ull;

    const int KT = (FIN + BK - 1) / BK;   // 545

    // ---- prologue: tile 0 -> stage 0 (k in [0,16) all valid) ----
    {
        float2 a0 = *(const float2*)(Xp);
        float2 a1 = *(const float2*)(Xp + 2);
        As[0][(la_k + 0) * BM + la_row] = a0.x;
        As[0][(la_k + 1) * BM + la_row] = a0.y;
        As[0][(la_k + 2) * BM + la_row] = a1.x;
        As[0][(la_k + 3) * BM + la_row] = a1.y;
#pragma unroll
        for (int q = 0; q < 4; q++) {
            int krow = q * 4 + wrp;                   // 0..15
            float4 b = *(const float4*)(W + (long)krow * HID + lane * 4);
            *(float4*)&Bs[0][krow * HID + lane * 4] = b;
        }
    }
    __syncthreads();

    for (int tile = 0; tile < KT; ++tile) {
        const int s = tile & 1;
        float2 pa0 = make_float2(0.f, 0.f), pa1 = make_float2(0.f, 0.f);
        float4 pb[4];
#pragma unroll
        for (int q = 0; q < 4; q++) pb[q] = make_float4(0.f, 0.f, 0.f, 0.f);
        const bool nx = (tile + 1 < KT);
        if (nx) {
            int k0 = (tile + 1) * BK;
            if (k0 + la_k     < FIN) pa0 = *(const float2*)(Xp + k0);
            if (k0 + la_k + 2 < FIN) pa1 = *(const float2*)(Xp + k0 + 2);
#pragma unroll
            for (int q = 0; q < 4; q++) {
                int krow = k0 + q * 4 + wrp;
                if (krow < FIN)
                    pb[q] = *(const float4*)(W + (long)krow * HID + lane * 4);
            }
        }

        // ---- compute on stage s ----
#pragma unroll
        for (int kk = 0; kk < BK; ++kk) {
            unsigned long long a0 = *(const unsigned long long*)&As[s][kk * BM + tm * 4];
            unsigned long long a1 = *(const unsigned long long*)&As[s][kk * BM + tm * 4 + 2];
            float4 b0 = *(const float4*)&Bs[s][kk * HID + tn * 8];
            float4 b1 = *(const float4*)&Bs[s][kk * HID + tn * 8 + 4];
            unsigned long long bb[8];
            bb[0] = pk2(b0.x); bb[1] = pk2(b0.y); bb[2] = pk2(b0.z); bb[3] = pk2(b0.w);
            bb[4] = pk2(b1.x); bb[5] = pk2(b1.y); bb[6] = pk2(b1.z); bb[7] = pk2(b1.w);
#pragma unroll
            for (int j = 0; j < 8; j++) {
                fma2(acc[0][j], a0, bb[j]);
                fma2(acc[1][j], a1, bb[j]);
            }
        }

        // ---- store next stage ----
        if (nx) {
            const int s2 = s ^ 1;
            As[s2][(la_k + 0) * BM + la_row] = pa0.x;
            As[s2][(la_k + 1) * BM + la_row] = pa0.y;
            As[s2][(la_k + 2) * BM + la_row] = pa1.x;
            As[s2][(la_k + 3) * BM + la_row] = pa1.y;
#pragma unroll
            for (int q = 0; q < 4; q++) {
                int krow = q * 4 + wrp;
                *(float4*)&Bs[s2][krow * HID + lane * 4] = pb[q];
            }
        }
        __syncthreads();
    }

    // ---- epilogue (grid is exactly 20000/32: no M guard needed) ----
#pragma unroll
    for (int p = 0; p < 2; p++) {
        int m0 = bm + tm * 4 + 2 * p;
        float r0[8], r1[8];
#pragma unroll
        for (int j = 0; j < 8; j++) {
            r0[j] = __uint_as_float((unsigned)(acc[p][j] & 0xffffffffull));
            r1[j] = __uint_as_float((unsigned)(acc[p][j] >> 32));
        }
        float4* o0 = (float4*)&d_H1[(long)m0 * HID + tn * 8];
        o0[0] = make_float4(r0[0], r0[1], r0[2], r0[3]);
        o0[1] = make_float4(r0[4], r0[5], r0[6], r0[7]);
        float4* o1 = (float4*)&d_H1[(long)(m0 + 1) * HID + tn * 8];
        o1[0] = make_float4(r1[0], r1[1], r1[2], r1[3]);
        o1[1] = make_float4(r1[4], r1[5], r1[6], r1[7]);
    }
}

// ---------------- aggregation 1: G1 = relu(Â H1 + b1), warp per node ------------
__global__ void k_agg1(const float* __restrict__ b1) {
    int gw   = (blockIdx.x * blockDim.x + threadIdx.x) >> 5;
    int lane = threadIdx.x & 31;
    if (gw >= NN) return;
    int v = gw;
    float dv = d_dinv[v];
    float w0 = dv * dv;
    float4 h = *(const float4*)&d_H1[(long)v * HID + lane * 4];
    float ax = h.x * w0, ay = h.y * w0, az = h.z * w0, aw = h.w * w0;
    int b = d_rowptr[v], e = d_rowptr[v + 1];
    for (int i = b; i < e; i++) {
        int s = d_col[i];
        float wi = d_dinv[s] * dv;
        float4 hs = *(const float4*)&d_H1[(long)s * HID + lane * 4];
        ax = fmaf(wi, hs.x, ax);
        ay = fmaf(wi, hs.y, ay);
        az = fmaf(wi, hs.z, az);
        aw = fmaf(wi, hs.w, aw);
    }
    float4 bb = *(const float4*)&b1[lane * 4];
    ax = fmaxf(ax + bb.x, 0.f);
    ay = fmaxf(ay + bb.y, 0.f);
    az = fmaxf(az + bb.z, 0.f);
    aw = fmaxf(aw + bb.w, 0.f);
    *(float4*)&d_G1[(long)v * HID + lane * 4] = make_float4(ax, ay, az, aw);
}

// ---------------- GEMM2: H2[20000,70] = G1[20000,128] @ W2[128,70] --------------
__global__ void __launch_bounds__(256) k_gemm2(const float* __restrict__ W2) {
    __shared__ float W2s[HID * 72];      // padded to 72 cols
    __shared__ float srow[8][HID];
    int t = threadIdx.x;
    for (int i = t; i < HID * NC; i += 256) {
        int k = i / NC, c = i - k * NC;
        W2s[k * 72 + c] = W2[i];
    }
    __syncthreads();
    int w = t >> 5, lane = t & 31;
    int row = blockIdx.x * 8 + w;        // grid 2500 -> rows 0..19999 exactly
    *(float4*)&srow[w][lane * 4] = *(const float4*)&d_G1[(long)row * HID + lane * 4];
    __syncwarp();
    float a0 = 0.f, a1 = 0.f, a2 = 0.f;
    int c0 = lane, c1 = lane + 32, c2 = lane + 64;
    bool v2 = (c2 < NC);
#pragma unroll 16
    for (int k = 0; k < HID; k++) {
        float x = srow[w][k];
        a0 = fmaf(x, W2s[k * 72 + c0], a0);
        a1 = fmaf(x, W2s[k * 72 + c1], a1);
        if (v2) a2 = fmaf(x, W2s[k * 72 + c2], a2);
    }
    d_H2[(long)row * NC + c0] = a0;
    d_H2[(long)row * NC + c1] = a1;
    if (v2) d_H2[(long)row * NC + c2] = a2;
}

// ---------------- aggregation 2 + bias + softmax, warp per node -----------------
__global__ void k_agg2(const float* __restrict__ b2, float* __restrict__ out) {
    int gw   = (blockIdx.x * blockDim.x + threadIdx.x) >> 5;
    int lane = threadIdx.x & 31;
    if (gw >= NN) return;
    int v = gw;
    float dv = d_dinv[v];
    float w0 = dv * dv;
    int c0 = lane, c1 = lane + 32, c2 = lane + 64;
    bool v2 = (c2 < NC);
    const float* H = d_H2;
    float a0 = H[(long)v * NC + c0] * w0;
    float a1 = H[(long)v * NC + c1] * w0;
    float a2 = v2 ? H[(long)v * NC + c2] * w0 : 0.f;
    int b = d_rowptr[v], e = d_rowptr[v + 1];
    for (int i = b; i < e; i++) {
        int s = d_col[i];
        float wi = d_dinv[s] * dv;
        long o = (long)s * NC;
        a0 = fmaf(wi, H[o + c0], a0);
        a1 = fmaf(wi, H[o + c1], a1);
        if (v2) a2 = fmaf(wi, H[o + c2], a2);
    }
    a0 += b2[c0];
    a1 += b2[c1];
    if (v2) a2 += b2[c2];

    float m = fmaxf(a0, a1);
    if (v2) m = fmaxf(m, a2);
#pragma unroll
    for (int off = 16; off > 0; off >>= 1)
        m = fmaxf(m, __shfl_xor_sync(0xffffffffu, m, off));
    float e0 = expf(a0 - m);
    float e1 = expf(a1 - m);
    float e2 = v2 ? expf(a2 - m) : 0.f;
    float ss = e0 + e1 + e2;
#pragma unroll
    for (int off = 16; off > 0; off >>= 1)
        ss += __shfl_xor_sync(0xffffffffu, ss, off);
    float inv = 1.f / ss;
    out[(long)v * NC + c0] = e0 * inv;
    out[(long)v * NC + c1] = e1 * inv;
    if (v2) out[(long)v * NC + c2] = e2 * inv;
}

// ---------------- launch ---------------------------------------------------------
extern "C" void kernel_launch(void* const* d_in, const int* in_sizes, int n_in,
                              void* d_out, int out_size) {
    const float* x     = (const float*)d_in[0];
    const int*   edges = (const int*)d_in[1];     // [2, E] row-major
    const float* W1    = (const float*)d_in[2];
    const float* b1    = (const float*)d_in[3];
    const float* W2    = (const float*)d_in[4];
    const float* b2    = (const float*)d_in[5];
    const int* src = edges;
    const int* dst = edges + NE;
    float* out = (float*)d_out;

    k_init_deg<<<(NN + 255) / 256, 256>>>();
    k_count  <<<(NE + 255) / 256, 256>>>(dst);
    k_dinv   <<<(NN + 255) / 256, 256>>>();
    k_scan   <<<1, 1024>>>();
    k_fill   <<<(NE + 255) / 256, 256>>>(src, dst);
    k_sort   <<<(NN + 255) / 256, 256>>>();

    k_gemm1  <<<NN / BM, 128>>>(x, W1);
    k_agg1   <<<(NN * 32 + 255) / 256, 256>>>(b1);
    k_gemm2  <<<NN / 8, 256>>>(W2);
    k_agg2   <<<(NN * 32 + 255) / 256, 256>>>(b2, out);
}

// round 9
// speedup vs baseline: 2.6423x; 2.6423x over previous
#include <cuda_runtime.h>
#include <cuda_bf16.h>
#include <stdint.h>

#define NN   20000
#define FIN  8710
#define HID  128
#define NC   70
#define NE   640000

#define KB    32                    // bf16 K per chunk
#define NCHK  273                   // ceil(8710/32)
#define WSTR  (NCHK * KB)           // 8736 padded K for W arrays

// GEMM1 tiling
#define BM    160                   // rows per CTA -> grid = 125 exactly
#define GRID1 (NN / BM)             // 125
#define AROW  80                    // smem row stride bytes (64B data + 16B pad)
#define ASZ   (BM * AROW)           // 12800
#define BSZ   (HID * AROW)          // 10240
#define STG   (2 * ASZ + 2 * BSZ)   // 46080 per stage
#define SMTOT (2 * STG)             // 92160

// ---------------- scratch (static device globals; no runtime alloc) -------------
__device__ float d_H1[NN * HID];
__device__ float d_G1[NN * HID];
__device__ float d_H2[NN * NC];
__device__ int   d_deg[NN];
__device__ float d_dinv[NN];
__device__ int   d_rowptr[NN + 1];
__device__ int   d_pos[NN];
__device__ int   d_col[NE];
__device__ __nv_bfloat16 d_Wh[HID * WSTR];   // [n][k] K-major transposed W1 hi
__device__ __nv_bfloat16 d_Wl[HID * WSTR];   // lo residual

// ================= helpers =======================================================
__device__ __forceinline__ uint32_t smem_u32(const void* p) {
    uint32_t a;
    asm("{ .reg .u64 t; cvta.to.shared.u64 t, %1; cvt.u32.u64 %0, t; }"
        : "=r"(a) : "l"(p));
    return a;
}
__device__ __forceinline__ void ldm_x4(uint32_t addr, uint32_t& r0, uint32_t& r1,
                                       uint32_t& r2, uint32_t& r3) {
    asm volatile("ldmatrix.sync.aligned.m8n8.x4.shared.b16 {%0,%1,%2,%3}, [%4];"
                 : "=r"(r0), "=r"(r1), "=r"(r2), "=r"(r3) : "r"(addr));
}
__device__ __forceinline__ void mma_bf16(float* c, const uint32_t* a, const uint32_t* b) {
    asm volatile("mma.sync.aligned.m16n8k16.row.col.f32.bf16.bf16.f32 "
                 "{%0,%1,%2,%3}, {%4,%5,%6,%7}, {%8,%9}, {%0,%1,%2,%3};"
                 : "+f"(c[0]), "+f"(c[1]), "+f"(c[2]), "+f"(c[3])
                 : "r"(a[0]), "r"(a[1]), "r"(a[2]), "r"(a[3]),
                   "r"(b[0]), "r"(b[1]));
}
__device__ __forceinline__ void split2(float2 v, uint32_t& h, uint32_t& l) {
    __nv_bfloat16 hx = __float2bfloat16(v.x);
    __nv_bfloat16 hy = __float2bfloat16(v.y);
    float rx = v.x - __bfloat162float(hx);
    float ry = v.y - __bfloat162float(hy);
    __nv_bfloat162 hp; hp.x = hx; hp.y = hy;
    __nv_bfloat162 lp; lp.x = __float2bfloat16(rx); lp.y = __float2bfloat16(ry);
    h = *(uint32_t*)&hp;
    l = *(uint32_t*)&lp;
}

// ---------------- degree / CSR build --------------------------------------------
__global__ void k_init_deg() {
    int i = blockIdx.x * blockDim.x + threadIdx.x;
    if (i < NN) d_deg[i] = 1;
}
__global__ void k_count(const int* __restrict__ dst) {
    int e = blockIdx.x * blockDim.x + threadIdx.x;
    if (e < NE) atomicAdd(&d_deg[dst[e]], 1);
}
__global__ void k_dinv() {
    int i = blockIdx.x * blockDim.x + threadIdx.x;
    if (i < NN) d_dinv[i] = rsqrtf((float)d_deg[i]);
}
__global__ void k_scan() {
    __shared__ int sm[1024];
    __shared__ int carry;
    int t = threadIdx.x;
    if (t == 0) carry = 0;
    __syncthreads();
    for (int base = 0; base < NN; base += 1024) {
        int i = base + t;
        int v = (i < NN) ? (d_deg[i] - 1) : 0;
        sm[t] = v;
        __syncthreads();
        for (int off = 1; off < 1024; off <<= 1) {
            int a = (t >= off) ? sm[t - off] : 0;
            __syncthreads();
            sm[t] += a;
            __syncthreads();
        }
        if (i < NN) {
            int ex = carry + sm[t] - v;
            d_rowptr[i] = ex;
            d_pos[i]    = ex;
        }
        __syncthreads();
        if (t == 1023) carry += sm[1023];
        __syncthreads();
    }
    if (t == 0) d_rowptr[NN] = carry;
}
__global__ void k_fill(const int* __restrict__ src, const int* __restrict__ dst) {
    int e = blockIdx.x * blockDim.x + threadIdx.x;
    if (e < NE) {
        int d    = dst[e];
        int slot = atomicAdd(&d_pos[d], 1);
        d_col[slot] = src[e];
    }
}
__global__ void k_sort() {
    int v = blockIdx.x * blockDim.x + threadIdx.x;
    if (v >= NN) return;
    int b = d_rowptr[v], e = d_rowptr[v + 1];
    for (int i = b + 1; i < e; i++) {
        int key = d_col[i];
        int j = i - 1;
        while (j >= b && d_col[j] > key) { d_col[j + 1] = d_col[j]; j--; }
        d_col[j + 1] = key;
    }
}

// ---------------- W1 split + transpose: d_Wh/d_Wl[n][k] --------------------------
__global__ void k_convW(const float* __restrict__ W1) {
    int i = blockIdx.x * blockDim.x + threadIdx.x;   // over HID*WSTR, n-fast
    if (i >= HID * WSTR) return;
    int n = i & (HID - 1);
    int k = i >> 7;
    float v = (k < FIN) ? W1[k * HID + n] : 0.0f;
    __nv_bfloat16 h = __float2bfloat16(v);
    __nv_bfloat16 l = __float2bfloat16(v - __bfloat162float(h));
    d_Wh[(size_t)n * WSTR + k] = h;
    d_Wl[(size_t)n * WSTR + k] = l;
}

// ---------------- GEMM1 via mma.sync bf16 3-way split ----------------------------
// H1[20000,128] = X @ W1. CTA: 160x128, 320 thr (10 warps = 5m x 2n, warp 32x64).
// smem stage layout: AH[160x80B] AL BH[128x80B] BL, double buffered.
__global__ void __launch_bounds__(320, 1) k_gemm1_mma(const float* __restrict__ X) {
    extern __shared__ char sm_[];
    const uint32_t sb = smem_u32(sm_);
    const int tid  = threadIdx.x;
    const int lane = tid & 31;
    const int wid  = tid >> 5;
    const int wm   = wid >> 1;          // 0..4
    const int wn   = wid & 1;           // 0..1
    const int bm   = blockIdx.x * BM;

    // fill mapping
    const int ar  = tid >> 1;                 // 0..159 A row
    const int aks = (tid & 1) << 4;           // 0/16 (elements)
    const float* xp = X + (size_t)(bm + ar) * FIN + aks;
    const int  bn  = tid >> 1;                // 0..127 (tid<256)
    const int  bks = (tid & 1) << 4;
    const bool bv  = tid < 256;
    const __nv_bfloat16* whp = d_Wh + (size_t)(bv ? bn : 0) * WSTR + bks;
    const __nv_bfloat16* wlp = d_Wl + (size_t)(bv ? bn : 0) * WSTR + bks;

    // ldmatrix per-lane offsets
    const int a_r     = lane & 15;
    const int a_kbyte = (lane >> 4) << 4;               // 0/16
    const uint32_t a_off = (uint32_t)((wm * 32 + a_r) * AROW + a_kbyte);
    const int b_r     = (lane & 7) + (((lane >> 4) & 1) << 3);
    const int b_kbyte = ((lane >> 3) & 1) << 4;         // 0/16
    const uint32_t b_off = (uint32_t)((wn * 64 + b_r) * AROW + b_kbyte);

    float acc[2][8][4];
#pragma unroll
    for (int mt = 0; mt < 2; mt++)
#pragma unroll
        for (int nt = 0; nt < 8; nt++)
#pragma unroll
            for (int q = 0; q < 4; q++) acc[mt][nt][q] = 0.f;

    float2 rA[8];
    uint4  rBh[2], rBl[2];

    auto ldgA = [&](int c) {
        const float* p = xp + c * KB;
        int kb = c * KB + aks;
#pragma unroll
        for (int j = 0; j < 8; j++)
            rA[j] = (kb + 2 * j < FIN) ? __ldg((const float2*)(p + 2 * j))
                                       : make_float2(0.f, 0.f);
    };
    auto ldgB = [&](int c) {
        if (bv) {
            rBh[0] = *(const uint4*)(whp + c * KB);
            rBh[1] = *(const uint4*)(whp + c * KB + 8);
            rBl[0] = *(const uint4*)(wlp + c * KB);
            rBl[1] = *(const uint4*)(wlp + c * KB + 8);
        }
    };
    auto sts = [&](int s) {
        char* p = sm_ + s * STG;
        uint32_t hi[8], lo[8];
#pragma unroll
        for (int j = 0; j < 8; j++) split2(rA[j], hi[j], lo[j]);
        uint32_t ao = (uint32_t)(ar * AROW + aks * 2);
        *(uint4*)(p + ao)            = make_uint4(hi[0], hi[1], hi[2], hi[3]);
        *(uint4*)(p + ao + 16)       = make_uint4(hi[4], hi[5], hi[6], hi[7]);
        *(uint4*)(p + ASZ + ao)      = make_uint4(lo[0], lo[1], lo[2], lo[3]);
        *(uint4*)(p + ASZ + ao + 16) = make_uint4(lo[4], lo[5], lo[6], lo[7]);
        if (bv) {
            uint32_t bo = (uint32_t)(bn * AROW + bks * 2);
            *(uint4*)(p + 2 * ASZ + bo)             = rBh[0];
            *(uint4*)(p + 2 * ASZ + bo + 16)        = rBh[1];
            *(uint4*)(p + 2 * ASZ + BSZ + bo)       = rBl[0];
            *(uint4*)(p + 2 * ASZ + BSZ + bo + 16)  = rBl[1];
        }
    };
    auto compute = [&](int s) {
        const uint32_t aH = sb + s * STG + a_off;
        const uint32_t aL = aH + ASZ;
        const uint32_t bH = sb + s * STG + 2 * ASZ + b_off;
        const uint32_t bL = bH + BSZ;
#pragma unroll
        for (int ks = 0; ks < 2; ks++) {
            uint32_t ah[2][4], al[2][4], bh[8][2], bl[8][2];
#pragma unroll
            for (int mt = 0; mt < 2; mt++) {
                ldm_x4(aH + mt * (16 * AROW) + ks * 32,
                       ah[mt][0], ah[mt][1], ah[mt][2], ah[mt][3]);
                ldm_x4(aL + mt * (16 * AROW) + ks * 32,
                       al[mt][0], al[mt][1], al[mt][2], al[mt][3]);
            }
#pragma unroll
            for (int bt = 0; bt < 4; bt++) {
                ldm_x4(bH + bt * (16 * AROW) + ks * 32,
                       bh[2 * bt][0], bh[2 * bt][1], bh[2 * bt + 1][0], bh[2 * bt + 1][1]);
                ldm_x4(bL + bt * (16 * AROW) + ks * 32,
                       bl[2 * bt][0], bl[2 * bt][1], bl[2 * bt + 1][0], bl[2 * bt + 1][1]);
            }
#pragma unroll
            for (int mt = 0; mt < 2; mt++)
#pragma unroll
                for (int nt = 0; nt < 8; nt++) {
                    mma_bf16(acc[mt][nt], ah[mt], bh[nt]);
                    mma_bf16(acc[mt][nt], ah[mt], bl[nt]);
                    mma_bf16(acc[mt][nt], al[mt], bh[nt]);
                }
        }
    };

    // prologue
    ldgA(0); ldgB(0); sts(0);
    __syncthreads();

    for (int c = 0; c < NCHK; ++c) {
        const int s = c & 1;
        if (c + 1 < NCHK) { ldgA(c + 1); ldgB(c + 1); }
        compute(s);
        if (c + 1 < NCHK) sts(s ^ 1);
        __syncthreads();
    }

    // epilogue: acc frag -> global (lane: row = l/4 (+8), col = (l%4)*2 (+1))
#pragma unroll
    for (int mt = 0; mt < 2; mt++)
#pragma unroll
        for (int nt = 0; nt < 8; nt++) {
            int row = bm + wm * 32 + mt * 16 + (lane >> 2);
            int col = wn * 64 + nt * 8 + (lane & 3) * 2;
            *(float2*)&d_H1[(size_t)row * HID + col] =
                make_float2(acc[mt][nt][0], acc[mt][nt][1]);
            *(float2*)&d_H1[(size_t)(row + 8) * HID + col] =
                make_float2(acc[mt][nt][2], acc[mt][nt][3]);
        }
}

// ---------------- aggregation 1: G1 = relu(Â H1 + b1), warp per node ------------
__global__ void k_agg1(const float* __restrict__ b1) {
    int gw   = (blockIdx.x * blockDim.x + threadIdx.x) >> 5;
    int lane = threadIdx.x & 31;
    if (gw >= NN) return;
    int v = gw;
    float dv = d_dinv[v];
    float w0 = dv * dv;
    float4 h = *(const float4*)&d_H1[(size_t)v * HID + lane * 4];
    float ax = h.x * w0, ay = h.y * w0, az = h.z * w0, aw = h.w * w0;
    int b = d_rowptr[v], e = d_rowptr[v + 1];
    for (int i = b; i < e; i++) {
        int s = d_col[i];
        float wi = d_dinv[s] * dv;
        float4 hs = *(const float4*)&d_H1[(size_t)s * HID + lane * 4];
        ax = fmaf(wi, hs.x, ax);
        ay = fmaf(wi, hs.y, ay);
        az = fmaf(wi, hs.z, az);
        aw = fmaf(wi, hs.w, aw);
    }
    float4 bb = *(const float4*)&b1[lane * 4];
    ax = fmaxf(ax + bb.x, 0.f);
    ay = fmaxf(ay + bb.y, 0.f);
    az = fmaxf(az + bb.z, 0.f);
    aw = fmaxf(aw + bb.w, 0.f);
    *(float4*)&d_G1[(size_t)v * HID + lane * 4] = make_float4(ax, ay, az, aw);
}

// ---------------- GEMM2: H2[20000,70] = G1[20000,128] @ W2[128,70] --------------
__global__ void __launch_bounds__(256) k_gemm2(const float* __restrict__ W2) {
    __shared__ float W2s[HID * 72];
    __shared__ float srow[8][HID];
    int t = threadIdx.x;
    for (int i = t; i < HID * NC; i += 256) {
        int k = i / NC, c = i - k * NC;
        W2s[k * 72 + c] = W2[i];
    }
    __syncthreads();
    int w = t >> 5, lane = t & 31;
    int row = blockIdx.x * 8 + w;
    *(float4*)&srow[w][lane * 4] = *(const float4*)&d_G1[(size_t)row * HID + lane * 4];
    __syncwarp();
    float a0 = 0.f, a1 = 0.f, a2 = 0.f;
    int c0 = lane, c1 = lane + 32, c2 = lane + 64;
    bool v2 = (c2 < NC);
#pragma unroll 16
    for (int k = 0; k < HID; k++) {
        float x = srow[w][k];
        a0 = fmaf(x, W2s[k * 72 + c0], a0);
        a1 = fmaf(x, W2s[k * 72 + c1], a1);
        if (v2) a2 = fmaf(x, W2s[k * 72 + c2], a2);
    }
    d_H2[(size_t)row * NC + c0] = a0;
    d_H2[(size_t)row * NC + c1] = a1;
    if (v2) d_H2[(size_t)row * NC + c2] = a2;
}

// ---------------- aggregation 2 + bias + softmax, warp per node -----------------
__global__ void k_agg2(const float* __restrict__ b2, float* __restrict__ out) {
    int gw   = (blockIdx.x * blockDim.x + threadIdx.x) >> 5;
    int lane = threadIdx.x & 31;
    if (gw >= NN) return;
    int v = gw;
    float dv = d_dinv[v];
    float w0 = dv * dv;
    int c0 = lane, c1 = lane + 32, c2 = lane + 64;
    bool v2 = (c2 < NC);
    const float* H = d_H2;
    float a0 = H[(size_t)v * NC + c0] * w0;
    float a1 = H[(size_t)v * NC + c1] * w0;
    float a2 = v2 ? H[(size_t)v * NC + c2] * w0 : 0.f;
    int b = d_rowptr[v], e = d_rowptr[v + 1];
    for (int i = b; i < e; i++) {
        int s = d_col[i];
        float wi = d_dinv[s] * dv;
        size_t o = (size_t)s * NC;
        a0 = fmaf(wi, H[o + c0], a0);
        a1 = fmaf(wi, H[o + c1], a1);
        if (v2) a2 = fmaf(wi, H[o + c2], a2);
    }
    a0 += b2[c0];
    a1 += b2[c1];
    if (v2) a2 += b2[c2];

    float m = fmaxf(a0, a1);
    if (v2) m = fmaxf(m, a2);
#pragma unroll
    for (int off = 16; off > 0; off >>= 1)
        m = fmaxf(m, __shfl_xor_sync(0xffffffffu, m, off));
    float e0 = expf(a0 - m);
    float e1 = expf(a1 - m);
    float e2 = v2 ? expf(a2 - m) : 0.f;
    float ss = e0 + e1 + e2;
#pragma unroll
    for (int off = 16; off > 0; off >>= 1)
        ss += __shfl_xor_sync(0xffffffffu, ss, off);
    float inv = 1.f / ss;
    out[(size_t)v * NC + c0] = e0 * inv;
    out[(size_t)v * NC + c1] = e1 * inv;
    if (v2) out[(size_t)v * NC + c2] = e2 * inv;
}

// ---------------- launch ---------------------------------------------------------
extern "C" void kernel_launch(void* const* d_in, const int* in_sizes, int n_in,
                              void* d_out, int out_size) {
    const float* x     = (const float*)d_in[0];
    const int*   edges = (const int*)d_in[1];
    const float* W1    = (const float*)d_in[2];
    const float* b1    = (const float*)d_in[3];
    const float* W2    = (const float*)d_in[4];
    const float* b2    = (const float*)d_in[5];
    const int* src = edges;
    const int* dst = edges + NE;
    float* out = (float*)d_out;

    k_init_deg<<<(NN + 255) / 256, 256>>>();
    k_count  <<<(NE + 255) / 256, 256>>>(dst);
    k_dinv   <<<(NN + 255) / 256, 256>>>();
    k_scan   <<<1, 1024>>>();
    k_fill   <<<(NE + 255) / 256, 256>>>(src, dst);
    k_sort   <<<(NN + 255) / 256, 256>>>();

    k_convW  <<<(HID * WSTR + 255) / 256, 256>>>(W1);

    static int smem_set = 0;
    if (!smem_set) {
        cudaFuncSetAttribute(k_gemm1_mma, cudaFuncAttributeMaxDynamicSharedMemorySize, SMTOT);
        smem_set = 1;
    }
    k_gemm1_mma<<<GRID1, 320, SMTOT>>>(x);

    k_agg1   <<<(NN * 32 + 255) / 256, 256>>>(b1);
    k_gemm2  <<<NN / 8, 256>>>(W2);
    k_agg2   <<<(NN * 32 + 255) / 256, 256>>>(b2, out);
}

// round 12
// speedup vs baseline: 3.1508x; 1.1924x over previous
#include <cuda_runtime.h>
#include <cuda_bf16.h>
#include <stdint.h>

#define NN   20000
#define FIN  8710
#define HID  128
#define NC   70
#define NE   640000

#define KB    32                    // bf16 K per chunk
#define NCHK  273                   // ceil(8710/32)
#define WSTR  (NCHK * KB)           // 8736 padded K for W arrays

// GEMM1 tiling
#define BM    160                   // rows per CTA -> grid = 125 exactly
#define GRID1 (NN / BM)             // 125
#define AROW  80                    // smem row stride bytes (64B data + 16B pad)
#define ASZ   (BM * AROW)           // 12800
#define BSZ   (HID * AROW)          // 10240
#define STG   (2 * ASZ + 2 * BSZ)   // 46080 per stage
#define SMTOT (2 * STG)             // 92160

// ---------------- scratch (static device globals; no runtime alloc) -------------
__device__ float d_H1[NN * HID];
__device__ float d_G1[NN * HID];
__device__ float d_H2[NN * NC];
__device__ int   d_deg[NN];
__device__ float d_dinv[NN];
__device__ int   d_rowptr[NN + 1];
__device__ int   d_pos[NN];
__device__ int   d_col[NE];
__device__ __nv_bfloat16 d_Wh[HID * WSTR];   // [n][k] K-major transposed W1 hi
__device__ __nv_bfloat16 d_Wl[HID * WSTR];   // lo residual

// ================= helpers =======================================================
__device__ __forceinline__ uint32_t smem_u32(const void* p) {
    uint32_t a;
    asm("{ .reg .u64 t; cvta.to.shared.u64 t, %1; cvt.u32.u64 %0, t; }"
        : "=r"(a) : "l"(p));
    return a;
}
__device__ __forceinline__ void ldm_x4(uint32_t addr, uint32_t& r0, uint32_t& r1,
                                       uint32_t& r2, uint32_t& r3) {
    asm volatile("ldmatrix.sync.aligned.m8n8.x4.shared.b16 {%0,%1,%2,%3}, [%4];"
                 : "=r"(r0), "=r"(r1), "=r"(r2), "=r"(r3) : "r"(addr));
}
__device__ __forceinline__ void mma_bf16(float* c, const uint32_t* a, const uint32_t* b) {
    asm volatile("mma.sync.aligned.m16n8k16.row.col.f32.bf16.bf16.f32 "
                 "{%0,%1,%2,%3}, {%4,%5,%6,%7}, {%8,%9}, {%0,%1,%2,%3};"
                 : "+f"(c[0]), "+f"(c[1]), "+f"(c[2]), "+f"(c[3])
                 : "r"(a[0]), "r"(a[1]), "r"(a[2]), "r"(a[3]),
                   "r"(b[0]), "r"(b[1]));
}
__device__ __forceinline__ void split2(float2 v, uint32_t& h, uint32_t& l) {
    __nv_bfloat16 hx = __float2bfloat16(v.x);
    __nv_bfloat16 hy = __float2bfloat16(v.y);
    float rx = v.x - __bfloat162float(hx);
    float ry = v.y - __bfloat162float(hy);
    __nv_bfloat162 hp; hp.x = hx; hp.y = hy;
    __nv_bfloat162 lp; lp.x = __float2bfloat16(rx); lp.y = __float2bfloat16(ry);
    h = *(uint32_t*)&hp;
    l = *(uint32_t*)&lp;
}

// ---------------- degree / CSR build --------------------------------------------
__global__ void k_init_deg() {
    int i = blockIdx.x * blockDim.x + threadIdx.x;
    if (i < NN) d_deg[i] = 1;
}
__global__ void k_count(const int* __restrict__ dst) {
    int e = blockIdx.x * blockDim.x + threadIdx.x;
    if (e < NE) atomicAdd(&d_deg[dst[e]], 1);
}
__global__ void k_dinv() {
    int i = blockIdx.x * blockDim.x + threadIdx.x;
    if (i < NN) d_dinv[i] = rsqrtf((float)d_deg[i]);
}
__global__ void k_scan() {
    __shared__ int sm[1024];
    __shared__ int carry;
    int t = threadIdx.x;
    if (t == 0) carry = 0;
    __syncthreads();
    for (int base = 0; base < NN; base += 1024) {
        int i = base + t;
        int v = (i < NN) ? (d_deg[i] - 1) : 0;
        sm[t] = v;
        __syncthreads();
        for (int off = 1; off < 1024; off <<= 1) {
            int a = (t >= off) ? sm[t - off] : 0;
            __syncthreads();
            sm[t] += a;
            __syncthreads();
        }
        if (i < NN) {
            int ex = carry + sm[t] - v;
            d_rowptr[i] = ex;
            d_pos[i]    = ex;
        }
        __syncthreads();
        if (t == 1023) carry += sm[1023];
        __syncthreads();
    }
    if (t == 0) d_rowptr[NN] = carry;
}
__global__ void k_fill(const int* __restrict__ src, const int* __restrict__ dst) {
    int e = blockIdx.x * blockDim.x + threadIdx.x;
    if (e < NE) {
        int d    = dst[e];
        int slot = atomicAdd(&d_pos[d], 1);
        d_col[slot] = src[e];
    }
}
__global__ void k_sort() {
    int v = blockIdx.x * blockDim.x + threadIdx.x;
    if (v >= NN) return;
    int b = d_rowptr[v], e = d_rowptr[v + 1];
    for (int i = b + 1; i < e; i++) {
        int key = d_col[i];
        int j = i - 1;
        while (j >= b && d_col[j] > key) { d_col[j + 1] = d_col[j]; j--; }
        d_col[j + 1] = key;
    }
}

// ---------------- W1 split + transpose: d_Wh/d_Wl[n][k] --------------------------
__global__ void k_convW(const float* __restrict__ W1) {
    int i = blockIdx.x * blockDim.x + threadIdx.x;   // over HID*WSTR, n-fast
    if (i >= HID * WSTR) return;
    int n = i & (HID - 1);
    int k = i >> 7;
    float v = (k < FIN) ? W1[k * HID + n] : 0.0f;
    __nv_bfloat16 h = __float2bfloat16(v);
    __nv_bfloat16 l = __float2bfloat16(v - __bfloat162float(h));
    d_Wh[(size_t)n * WSTR + k] = h;
    d_Wl[(size_t)n * WSTR + k] = l;
}

// ---------------- GEMM1 via mma.sync bf16 3-way split ----------------------------
// H1[20000,128] = X @ W1. CTA: 160x128, 320 thr (10 warps = 5m x 2n, warp 32x64).
// smem stage layout: AH[160x80B] AL BH[128x80B] BL, double buffered.
__global__ void __launch_bounds__(320, 1) k_gemm1_mma(const float* __restrict__ X) {
    extern __shared__ char sm_[];
    const uint32_t sb = smem_u32(sm_);
    const int tid  = threadIdx.x;
    const int lane = tid & 31;
    const int wid  = tid >> 5;
    const int wm   = wid >> 1;          // 0..4
    const int wn   = wid & 1;           // 0..1
    const int bm   = blockIdx.x * BM;

    // fill mapping
    const int ar  = tid >> 1;                 // 0..159 A row
    const int aks = (tid & 1) << 4;           // 0/16 (elements)
    const float* xp = X + (size_t)(bm + ar) * FIN + aks;
    const int  bn  = tid >> 1;                // 0..127 (tid<256)
    const int  bks = (tid & 1) << 4;
    const bool bv  = tid < 256;
    const __nv_bfloat16* whp = d_Wh + (size_t)(bv ? bn : 0) * WSTR + bks;
    const __nv_bfloat16* wlp = d_Wl + (size_t)(bv ? bn : 0) * WSTR + bks;

    // ldmatrix per-lane offsets
    const int a_r     = lane & 15;
    const int a_kbyte = (lane >> 4) << 4;               // 0/16
    const uint32_t a_off = (uint32_t)((wm * 32 + a_r) * AROW + a_kbyte);
    const int b_r     = (lane & 7) + (((lane >> 4) & 1) << 3);
    const int b_kbyte = ((lane >> 3) & 1) << 4;         // 0/16
    const uint32_t b_off = (uint32_t)((wn * 64 + b_r) * AROW + b_kbyte);

    float acc[2][8][4];
#pragma unroll
    for (int mt = 0; mt < 2; mt++)
#pragma unroll
        for (int nt = 0; nt < 8; nt++)
#pragma unroll
            for (int q = 0; q < 4; q++) acc[mt][nt][q] = 0.f;

    float2 rA[8];
    uint4  rBh[2], rBl[2];

    auto ldgA = [&](int c) {
        const float* p = xp + c * KB;
        int kb = c * KB + aks;
#pragma unroll
        for (int j = 0; j < 8; j++)
            rA[j] = (kb + 2 * j < FIN) ? __ldg((const float2*)(p + 2 * j))
                                       : make_float2(0.f, 0.f);
    };
    auto ldgB = [&](int c) {
        if (bv) {
            rBh[0] = *(const uint4*)(whp + c * KB);
            rBh[1] = *(const uint4*)(whp + c * KB + 8);
            rBl[0] = *(const uint4*)(wlp + c * KB);
            rBl[1] = *(const uint4*)(wlp + c * KB + 8);
        }
    };
    auto sts = [&](int s) {
        char* p = sm_ + s * STG;
        uint32_t hi[8], lo[8];
#pragma unroll
        for (int j = 0; j < 8; j++) split2(rA[j], hi[j], lo[j]);
        uint32_t ao = (uint32_t)(ar * AROW + aks * 2);
        *(uint4*)(p + ao)            = make_uint4(hi[0], hi[1], hi[2], hi[3]);
        *(uint4*)(p + ao + 16)       = make_uint4(hi[4], hi[5], hi[6], hi[7]);
        *(uint4*)(p + ASZ + ao)      = make_uint4(lo[0], lo[1], lo[2], lo[3]);
        *(uint4*)(p + ASZ + ao + 16) = make_uint4(lo[4], lo[5], lo[6], lo[7]);
        if (bv) {
            uint32_t bo = (uint32_t)(bn * AROW + bks * 2);
            *(uint4*)(p + 2 * ASZ + bo)             = rBh[0];
            *(uint4*)(p + 2 * ASZ + bo + 16)        = rBh[1];
            *(uint4*)(p + 2 * ASZ + BSZ + bo)       = rBl[0];
            *(uint4*)(p + 2 * ASZ + BSZ + bo + 16)  = rBl[1];
        }
    };
    auto compute = [&](int s) {
        const uint32_t aH = sb + s * STG + a_off;
        const uint32_t aL = aH + ASZ;
        const uint32_t bH = sb + s * STG + 2 * ASZ + b_off;
        const uint32_t bL = bH + BSZ;
#pragma unroll
        for (int ks = 0; ks < 2; ks++) {
            uint32_t ah[2][4], al[2][4], bh[8][2], bl[8][2];
#pragma unroll
            for (int mt = 0; mt < 2; mt++) {
                ldm_x4(aH + mt * (16 * AROW) + ks * 32,
                       ah[mt][0], ah[mt][1], ah[mt][2], ah[mt][3]);
                ldm_x4(aL + mt * (16 * AROW) + ks * 32,
                       al[mt][0], al[mt][1], al[mt][2], al[mt][3]);
            }
#pragma unroll
            for (int bt = 0; bt < 4; bt++) {
                ldm_x4(bH + bt * (16 * AROW) + ks * 32,
                       bh[2 * bt][0], bh[2 * bt][1], bh[2 * bt + 1][0], bh[2 * bt + 1][1]);
                ldm_x4(bL + bt * (16 * AROW) + ks * 32,
                       bl[2 * bt][0], bl[2 * bt][1], bl[2 * bt + 1][0], bl[2 * bt + 1][1]);
            }
#pragma unroll
            for (int mt = 0; mt < 2; mt++)
#pragma unroll
                for (int nt = 0; nt < 8; nt++) {
                    mma_bf16(acc[mt][nt], ah[mt], bh[nt]);
                    mma_bf16(acc[mt][nt], ah[mt], bl[nt]);
                    mma_bf16(acc[mt][nt], al[mt], bh[nt]);
                }
        }
    };

    // prologue
    ldgA(0); ldgB(0); sts(0);
    __syncthreads();

    for (int c = 0; c < NCHK; ++c) {
        const int s = c & 1;
        if (c + 1 < NCHK) { ldgA(c + 1); ldgB(c + 1); }
        compute(s);
        if (c + 1 < NCHK) sts(s ^ 1);
        __syncthreads();
    }

    // epilogue: acc frag -> global (lane: row = l/4 (+8), col = (l%4)*2 (+1))
#pragma unroll
    for (int mt = 0; mt < 2; mt++)
#pragma unroll
        for (int nt = 0; nt < 8; nt++) {
            int row = bm + wm * 32 + mt * 16 + (lane >> 2);
            int col = wn * 64 + nt * 8 + (lane & 3) * 2;
            *(float2*)&d_H1[(size_t)row * HID + col] =
                make_float2(acc[mt][nt][0], acc[mt][nt][1]);
            *(float2*)&d_H1[(size_t)(row + 8) * HID + col] =
                make_float2(acc[mt][nt][2], acc[mt][nt][3]);
        }
}

// ---------------- aggregation 1: G1 = relu(Â H1 + b1), warp per node ------------
__global__ void k_agg1(const float* __restrict__ b1) {
    int gw   = (blockIdx.x * blockDim.x + threadIdx.x) >> 5;
    int lane = threadIdx.x & 31;
    if (gw >= NN) return;
    int v = gw;
    float dv = d_dinv[v];
    float w0 = dv * dv;
    float4 h = *(const float4*)&d_H1[(size_t)v * HID + lane * 4];
    float ax = h.x * w0, ay = h.y * w0, az = h.z * w0, aw = h.w * w0;
    int b = d_rowptr[v], e = d_rowptr[v + 1];
    for (int i = b; i < e; i++) {
        int s = d_col[i];
        float wi = d_dinv[s] * dv;
        float4 hs = *(const float4*)&d_H1[(size_t)s * HID + lane * 4];
        ax = fmaf(wi, hs.x, ax);
        ay = fmaf(wi, hs.y, ay);
        az = fmaf(wi, hs.z, az);
        aw = fmaf(wi, hs.w, aw);
    }
    float4 bb = *(const float4*)&b1[lane * 4];
    ax = fmaxf(ax + bb.x, 0.f);
    ay = fmaxf(ay + bb.y, 0.f);
    az = fmaxf(az + bb.z, 0.f);
    aw = fmaxf(aw + bb.w, 0.f);
    *(float4*)&d_G1[(size_t)v * HID + lane * 4] = make_float4(ax, ay, az, aw);
}

// ---------------- GEMM2: H2[20000,70] = G1[20000,128] @ W2[128,70] --------------
__global__ void __launch_bounds__(256) k_gemm2(const float* __restrict__ W2) {
    __shared__ float W2s[HID * 72];
    __shared__ float srow[8][HID];
    int t = threadIdx.x;
    for (int i = t; i < HID * NC; i += 256) {
        int k = i / NC, c = i - k * NC;
        W2s[k * 72 + c] = W2[i];
    }
    __syncthreads();
    int w = t >> 5, lane = t & 31;
    int row = blockIdx.x * 8 + w;
    *(float4*)&srow[w][lane * 4] = *(const float4*)&d_G1[(size_t)row * HID + lane * 4];
    __syncwarp();
    float a0 = 0.f, a1 = 0.f, a2 = 0.f;
    int c0 = lane, c1 = lane + 32, c2 = lane + 64;
    bool v2 = (c2 < NC);
#pragma unroll 16
    for (int k = 0; k < HID; k++) {
        float x = srow[w][k];
        a0 = fmaf(x, W2s[k * 72 + c0], a0);
        a1 = fmaf(x, W2s[k * 72 + c1], a1);
        if (v2) a2 = fmaf(x, W2s[k * 72 + c2], a2);
    }
    d_H2[(size_t)row * NC + c0] = a0;
    d_H2[(size_t)row * NC + c1] = a1;
    if (v2) d_H2[(size_t)row * NC + c2] = a2;
}

// ---------------- aggregation 2 + bias + softmax, warp per node -----------------
__global__ void k_agg2(const float* __restrict__ b2, float* __restrict__ out) {
    int gw   = (blockIdx.x * blockDim.x + threadIdx.x) >> 5;
    int lane = threadIdx.x & 31;
    if (gw >= NN) return;
    int v = gw;
    float dv = d_dinv[v];
    float w0 = dv * dv;
    int c0 = lane, c1 = lane + 32, c2 = lane + 64;
    bool v2 = (c2 < NC);
    const float* H = d_H2;
    float a0 = H[(size_t)v * NC + c0] * w0;
    float a1 = H[(size_t)v * NC + c1] * w0;
    float a2 = v2 ? H[(size_t)v * NC + c2] * w0 : 0.f;
    int b = d_rowptr[v], e = d_rowptr[v + 1];
    for (int i = b; i < e; i++) {
        int s = d_col[i];
        float wi = d_dinv[s] * dv;
        size_t o = (size_t)s * NC;
        a0 = fmaf(wi, H[o + c0], a0);
        a1 = fmaf(wi, H[o + c1], a1);
        if (v2) a2 = fmaf(wi, H[o + c2], a2);
    }
    a0 += b2[c0];
    a1 += b2[c1];
    if (v2) a2 += b2[c2];

    float m = fmaxf(a0, a1);
    if (v2) m = fmaxf(m, a2);
#pragma unroll
    for (int off = 16; off > 0; off >>= 1)
        m = fmaxf(m, __shfl_xor_sync(0xffffffffu, m, off));
    float e0 = expf(a0 - m);
    float e1 = expf(a1 - m);
    float e2 = v2 ? expf(a2 - m) : 0.f;
    float ss = e0 + e1 + e2;
#pragma unroll
    for (int off = 16; off > 0; off >>= 1)
        ss += __shfl_xor_sync(0xffffffffu, ss, off);
    float inv = 1.f / ss;
    out[(size_t)v * NC + c0] = e0 * inv;
    out[(size_t)v * NC + c1] = e1 * inv;
    if (v2) out[(size_t)v * NC + c2] = e2 * inv;
}

// ---------------- launch ---------------------------------------------------------
extern "C" void kernel_launch(void* const* d_in, const int* in_sizes, int n_in,
                              void* d_out, int out_size) {
    const float* x     = (const float*)d_in[0];
    const int*   edges = (const int*)d_in[1];
    const float* W1    = (const float*)d_in[2];
    const float* b1    = (const float*)d_in[3];
    const float* W2    = (const float*)d_in[4];
    const float* b2    = (const float*)d_in[5];
    const int* src = edges;
    const int* dst = edges + NE;
    float* out = (float*)d_out;

    // one-time host-side setup (no device allocation; streams/events are host objs)
    static cudaStream_t s_side = 0;
    static cudaEvent_t  ev_fork = 0, ev_join = 0;
    static int inited = 0;
    if (!inited) {
        cudaStreamCreateWithFlags(&s_side, cudaStreamNonBlocking);
        cudaEventCreateWithFlags(&ev_fork, cudaEventDisableTiming);
        cudaEventCreateWithFlags(&ev_join, cudaEventDisableTiming);
        cudaFuncSetAttribute(k_gemm1_mma, cudaFuncAttributeMaxDynamicSharedMemorySize, SMTOT);
        inited = 1;
    }

    // fork: CSR build chain runs concurrently with convW + GEMM1
    cudaEventRecord(ev_fork, 0);
    cudaStreamWaitEvent(s_side, ev_fork, 0);

    k_init_deg<<<(NN + 255) / 256, 256, 0, s_side>>>();
    k_count  <<<(NE + 255) / 256, 256, 0, s_side>>>(dst);
    k_dinv   <<<(NN + 255) / 256, 256, 0, s_side>>>();
    k_scan   <<<1, 1024, 0, s_side>>>();
    k_fill   <<<(NE + 255) / 256, 256, 0, s_side>>>(src, dst);
    k_sort   <<<(NN + 255) / 256, 256, 0, s_side>>>();
    cudaEventRecord(ev_join, s_side);

    // main stream: dense path
    k_convW  <<<(HID * WSTR + 255) / 256, 256>>>(W1);
    k_gemm1_mma<<<GRID1, 320, SMTOT>>>(x);

    // join: aggregation needs both H1 and CSR
    cudaStreamWaitEvent(0, ev_join, 0);

    k_agg1   <<<(NN * 32 + 255) / 256, 256>>>(b1);
    k_gemm2  <<<NN / 8, 256>>>(W2);
    k_agg2   <<<(NN * 32 + 255) / 256, 256>>>(b2, out);
}

// round 13
// speedup vs baseline: 3.9293x; 1.2471x over previous
#include <cuda_runtime.h>
#include <cuda_fp16.h>
#include <stdint.h>

#define NN   20000
#define FIN  8710
#define HID  128
#define NC   70
#define NE   640000

#define KB    32                    // fp16 K per chunk
#define NCHK  273                   // ceil(8710/32)
#define WSTR  (NCHK * KB)           // 8736 padded K for W array

// GEMM1 tiling
#define BM    160                   // rows per CTA -> grid = 125 exactly
#define GRID1 (NN / BM)             // 125
#define AROW  80                    // smem row stride bytes (64B data + 16B pad)
#define ASZ   (BM * AROW)           // 12800
#define BSZ   (HID * AROW)          // 10240
#define STG   (2 * ASZ + BSZ)       // 35840 per stage (A_hi, A_lo, B)
#define SMTOT (2 * STG)             // 71680

// ---------------- scratch (static device globals; no runtime alloc) -------------
__device__ float d_H1[NN * HID];
__device__ float d_G1[NN * HID];
__device__ float d_H2[NN * NC];
__device__ int   d_deg[NN];
__device__ float d_dinv[NN];
__device__ int   d_rowptr[NN + 1];
__device__ int   d_pos[NN];
__device__ int   d_col[NE];
__device__ __half d_Wf[HID * WSTR];          // [n][k] K-major transposed W1 (fp16)

// ================= helpers =======================================================
__device__ __forceinline__ uint32_t smem_u32(const void* p) {
    uint32_t a;
    asm("{ .reg .u64 t; cvta.to.shared.u64 t, %1; cvt.u32.u64 %0, t; }"
        : "=r"(a) : "l"(p));
    return a;
}
__device__ __forceinline__ void ldm_x4(uint32_t addr, uint32_t& r0, uint32_t& r1,
                                       uint32_t& r2, uint32_t& r3) {
    asm volatile("ldmatrix.sync.aligned.m8n8.x4.shared.b16 {%0,%1,%2,%3}, [%4];"
                 : "=r"(r0), "=r"(r1), "=r"(r2), "=r"(r3) : "r"(addr));
}
__device__ __forceinline__ void mma_f16(float* c, const uint32_t* a, const uint32_t* b) {
    asm volatile("mma.sync.aligned.m16n8k16.row.col.f32.f16.f16.f32 "
                 "{%0,%1,%2,%3}, {%4,%5,%6,%7}, {%8,%9}, {%0,%1,%2,%3};"
                 : "+f"(c[0]), "+f"(c[1]), "+f"(c[2]), "+f"(c[3])
                 : "r"(a[0]), "r"(a[1]), "r"(a[2]), "r"(a[3]),
                   "r"(b[0]), "r"(b[1]));
}
__device__ __forceinline__ void split2h(float2 v, uint32_t& h, uint32_t& l) {
    __half hx = __float2half_rn(v.x);
    __half hy = __float2half_rn(v.y);
    float rx = v.x - __half2float(hx);
    float ry = v.y - __half2float(hy);
    __half2 hp; hp.x = hx; hp.y = hy;
    __half2 lp; lp.x = __float2half_rn(rx); lp.y = __float2half_rn(ry);
    h = *(uint32_t*)&hp;
    l = *(uint32_t*)&lp;
}

// ---------------- degree / CSR build --------------------------------------------
__global__ void k_init_deg() {
    int i = blockIdx.x * blockDim.x + threadIdx.x;
    if (i < NN) d_deg[i] = 1;
}
__global__ void k_count(const int* __restrict__ dst) {
    int e = blockIdx.x * blockDim.x + threadIdx.x;
    if (e < NE) atomicAdd(&d_deg[dst[e]], 1);
}
__global__ void k_dinv() {
    int i = blockIdx.x * blockDim.x + threadIdx.x;
    if (i < NN) d_dinv[i] = rsqrtf((float)d_deg[i]);
}
__global__ void k_scan() {
    __shared__ int sm[1024];
    __shared__ int carry;
    int t = threadIdx.x;
    if (t == 0) carry = 0;
    __syncthreads();
    for (int base = 0; base < NN; base += 1024) {
        int i = base + t;
        int v = (i < NN) ? (d_deg[i] - 1) : 0;
        sm[t] = v;
        __syncthreads();
        for (int off = 1; off < 1024; off <<= 1) {
            int a = (t >= off) ? sm[t - off] : 0;
            __syncthreads();
            sm[t] += a;
            __syncthreads();
        }
        if (i < NN) {
            int ex = carry + sm[t] - v;
            d_rowptr[i] = ex;
            d_pos[i]    = ex;
        }
        __syncthreads();
        if (t == 1023) carry += sm[1023];
        __syncthreads();
    }
    if (t == 0) d_rowptr[NN] = carry;
}
__global__ void k_fill(const int* __restrict__ src, const int* __restrict__ dst) {
    int e = blockIdx.x * blockDim.x + threadIdx.x;
    if (e < NE) {
        int d    = dst[e];
        int slot = atomicAdd(&d_pos[d], 1);
        d_col[slot] = src[e];
    }
}
__global__ void k_sort() {
    int v = blockIdx.x * blockDim.x + threadIdx.x;
    if (v >= NN) return;
    int b = d_rowptr[v], e = d_rowptr[v + 1];
    for (int i = b + 1; i < e; i++) {
        int key = d_col[i];
        int j = i - 1;
        while (j >= b && d_col[j] > key) { d_col[j + 1] = d_col[j]; j--; }
        d_col[j + 1] = key;
    }
}

// ---------------- W1 convert + transpose: d_Wf[n][k] (fp16) ----------------------
__global__ void k_convW(const float* __restrict__ W1) {
    int i = blockIdx.x * blockDim.x + threadIdx.x;   // over HID*WSTR, n-fast
    if (i >= HID * WSTR) return;
    int n = i & (HID - 1);
    int k = i >> 7;
    float v = (k < FIN) ? W1[k * HID + n] : 0.0f;
    d_Wf[(size_t)n * WSTR + k] = __float2half_rn(v);
}

// ---------------- GEMM1 via mma.sync fp16 2-way split ----------------------------
// H1[20000,128] = X @ W1. CTA: 160x128, 320 thr (10 warps = 5m x 2n, warp 32x64).
// A = Ah + Al (fp16 split, exact), B single fp16. acc += Ah*B; acc += Al*B.
// smem stage layout: AH[160x80B] AL[160x80B] B[128x80B], double buffered.
__global__ void __launch_bounds__(320, 1) k_gemm1_mma(const float* __restrict__ X) {
    extern __shared__ char sm_[];
    const uint32_t sb = smem_u32(sm_);
    const int tid  = threadIdx.x;
    const int lane = tid & 31;
    const int wid  = tid >> 5;
    const int wm   = wid >> 1;          // 0..4
    const int wn   = wid & 1;           // 0..1
    const int bm   = blockIdx.x * BM;

    // fill mapping
    const int ar  = tid >> 1;                 // 0..159 A row
    const int aks = (tid & 1) << 4;           // 0/16 (elements)
    const float* xp = X + (size_t)(bm + ar) * FIN + aks;
    const int  bn  = tid >> 1;                // 0..127 (tid<256)
    const int  bks = (tid & 1) << 4;
    const bool bv  = tid < 256;
    const __half* wfp = d_Wf + (size_t)(bv ? bn : 0) * WSTR + bks;

    // ldmatrix per-lane offsets
    const int a_r     = lane & 15;
    const int a_kbyte = (lane >> 4) << 4;               // 0/16
    const uint32_t a_off = (uint32_t)((wm * 32 + a_r) * AROW + a_kbyte);
    const int b_r     = (lane & 7) + (((lane >> 4) & 1) << 3);
    const int b_kbyte = ((lane >> 3) & 1) << 4;         // 0/16
    const uint32_t b_off = (uint32_t)((wn * 64 + b_r) * AROW + b_kbyte);

    float acc[2][8][4];
#pragma unroll
    for (int mt = 0; mt < 2; mt++)
#pragma unroll
        for (int nt = 0; nt < 8; nt++)
#pragma unroll
            for (int q = 0; q < 4; q++) acc[mt][nt][q] = 0.f;

    float2 rA[8];
    uint4  rBf[2];

    auto ldgA = [&](int c) {
        const float* p = xp + c * KB;
        int kb = c * KB + aks;
#pragma unroll
        for (int j = 0; j < 8; j++)
            rA[j] = (kb + 2 * j < FIN) ? __ldg((const float2*)(p + 2 * j))
                                       : make_float2(0.f, 0.f);
    };
    auto ldgB = [&](int c) {
        if (bv) {
            rBf[0] = *(const uint4*)(wfp + c * KB);
            rBf[1] = *(const uint4*)(wfp + c * KB + 8);
        }
    };
    auto sts = [&](int s) {
        char* p = sm_ + s * STG;
        uint32_t hi[8], lo[8];
#pragma unroll
        for (int j = 0; j < 8; j++) split2h(rA[j], hi[j], lo[j]);
        uint32_t ao = (uint32_t)(ar * AROW + aks * 2);
        *(uint4*)(p + ao)            = make_uint4(hi[0], hi[1], hi[2], hi[3]);
        *(uint4*)(p + ao + 16)       = make_uint4(hi[4], hi[5], hi[6], hi[7]);
        *(uint4*)(p + ASZ + ao)      = make_uint4(lo[0], lo[1], lo[2], lo[3]);
        *(uint4*)(p + ASZ + ao + 16) = make_uint4(lo[4], lo[5], lo[6], lo[7]);
        if (bv) {
            uint32_t bo = (uint32_t)(bn * AROW + bks * 2);
            *(uint4*)(p + 2 * ASZ + bo)      = rBf[0];
            *(uint4*)(p + 2 * ASZ + bo + 16) = rBf[1];
        }
    };
    auto compute = [&](int s) {
        const uint32_t aH = sb + s * STG + a_off;
        const uint32_t aL = aH + ASZ;
        const uint32_t bB = sb + s * STG + 2 * ASZ + b_off;
#pragma unroll
        for (int ks = 0; ks < 2; ks++) {
            uint32_t ah[2][4], al[2][4], bh[8][2];
#pragma unroll
            for (int mt = 0; mt < 2; mt++) {
                ldm_x4(aH + mt * (16 * AROW) + ks * 32,
                       ah[mt][0], ah[mt][1], ah[mt][2], ah[mt][3]);
                ldm_x4(aL + mt * (16 * AROW) + ks * 32,
                       al[mt][0], al[mt][1], al[mt][2], al[mt][3]);
            }
#pragma unroll
            for (int bt = 0; bt < 4; bt++) {
                ldm_x4(bB + bt * (16 * AROW) + ks * 32,
                       bh[2 * bt][0], bh[2 * bt][1], bh[2 * bt + 1][0], bh[2 * bt + 1][1]);
            }
#pragma unroll
            for (int mt = 0; mt < 2; mt++)
#pragma unroll
                for (int nt = 0; nt < 8; nt++) {
                    mma_f16(acc[mt][nt], ah[mt], bh[nt]);
                    mma_f16(acc[mt][nt], al[mt], bh[nt]);
                }
        }
    };

    // prologue
    ldgA(0); ldgB(0); sts(0);
    __syncthreads();

    for (int c = 0; c < NCHK; ++c) {
        const int s = c & 1;
        if (c + 1 < NCHK) { ldgA(c + 1); ldgB(c + 1); }
        compute(s);
        if (c + 1 < NCHK) sts(s ^ 1);
        __syncthreads();
    }

    // epilogue: acc frag -> global (lane: row = l/4 (+8), col = (l%4)*2 (+1))
#pragma unroll
    for (int mt = 0; mt < 2; mt++)
#pragma unroll
        for (int nt = 0; nt < 8; nt++) {
            int row = bm + wm * 32 + mt * 16 + (lane >> 2);
            int col = wn * 64 + nt * 8 + (lane & 3) * 2;
            *(float2*)&d_H1[(size_t)row * HID + col] =
                make_float2(acc[mt][nt][0], acc[mt][nt][1]);
            *(float2*)&d_H1[(size_t)(row + 8) * HID + col] =
                make_float2(acc[mt][nt][2], acc[mt][nt][3]);
        }
}

// ---------------- aggregation 1: G1 = relu(Â H1 + b1), warp per node ------------
__global__ void k_agg1(const float* __restrict__ b1) {
    int gw   = (blockIdx.x * blockDim.x + threadIdx.x) >> 5;
    int lane = threadIdx.x & 31;
    if (gw >= NN) return;
    int v = gw;
    float dv = d_dinv[v];
    float w0 = dv * dv;
    float4 h = *(const float4*)&d_H1[(size_t)v * HID + lane * 4];
    float ax = h.x * w0, ay = h.y * w0, az = h.z * w0, aw = h.w * w0;
    int b = d_rowptr[v], e = d_rowptr[v + 1];
    for (int i = b; i < e; i++) {
        int s = d_col[i];
        float wi = d_dinv[s] * dv;
        float4 hs = *(const float4*)&d_H1[(size_t)s * HID + lane * 4];
        ax = fmaf(wi, hs.x, ax);
        ay = fmaf(wi, hs.y, ay);
        az = fmaf(wi, hs.z, az);
        aw = fmaf(wi, hs.w, aw);
    }
    float4 bb = *(const float4*)&b1[lane * 4];
    ax = fmaxf(ax + bb.x, 0.f);
    ay = fmaxf(ay + bb.y, 0.f);
    az = fmaxf(az + bb.z, 0.f);
    aw = fmaxf(aw + bb.w, 0.f);
    *(float4*)&d_G1[(size_t)v * HID + lane * 4] = make_float4(ax, ay, az, aw);
}

// ---------------- GEMM2: H2[20000,70] = G1[20000,128] @ W2[128,70] --------------
__global__ void __launch_bounds__(256) k_gemm2(const float* __restrict__ W2) {
    __shared__ float W2s[HID * 72];
    __shared__ float srow[8][HID];
    int t = threadIdx.x;
    for (int i = t; i < HID * NC; i += 256) {
        int k = i / NC, c = i - k * NC;
        W2s[k * 72 + c] = W2[i];
    }
    __syncthreads();
    int w = t >> 5, lane = t & 31;
    int row = blockIdx.x * 8 + w;
    *(float4*)&srow[w][lane * 4] = *(const float4*)&d_G1[(size_t)row * HID + lane * 4];
    __syncwarp();
    float a0 = 0.f, a1 = 0.f, a2 = 0.f;
    int c0 = lane, c1 = lane + 32, c2 = lane + 64;
    bool v2 = (c2 < NC);
#pragma unroll 16
    for (int k = 0; k < HID; k++) {
        float x = srow[w][k];
        a0 = fmaf(x, W2s[k * 72 + c0], a0);
        a1 = fmaf(x, W2s[k * 72 + c1], a1);
        if (v2) a2 = fmaf(x, W2s[k * 72 + c2], a2);
    }
    d_H2[(size_t)row * NC + c0] = a0;
    d_H2[(size_t)row * NC + c1] = a1;
    if (v2) d_H2[(size_t)row * NC + c2] = a2;
}

// ---------------- aggregation 2 + bias + softmax, warp per node -----------------
__global__ void k_agg2(const float* __restrict__ b2, float* __restrict__ out) {
    int gw   = (blockIdx.x * blockDim.x + threadIdx.x) >> 5;
    int lane = threadIdx.x & 31;
    if (gw >= NN) return;
    int v = gw;
    float dv = d_dinv[v];
    float w0 = dv * dv;
    int c0 = lane, c1 = lane + 32, c2 = lane + 64;
    bool v2 = (c2 < NC);
    const float* H = d_H2;
    float a0 = H[(size_t)v * NC + c0] * w0;
    float a1 = H[(size_t)v * NC + c1] * w0;
    float a2 = v2 ? H[(size_t)v * NC + c2] * w0 : 0.f;
    int b = d_rowptr[v], e = d_rowptr[v + 1];
    for (int i = b; i < e; i++) {
        int s = d_col[i];
        float wi = d_dinv[s] * dv;
        size_t o = (size_t)s * NC;
        a0 = fmaf(wi, H[o + c0], a0);
        a1 = fmaf(wi, H[o + c1], a1);
        if (v2) a2 = fmaf(wi, H[o + c2], a2);
    }
    a0 += b2[c0];
    a1 += b2[c1];
    if (v2) a2 += b2[c2];

    float m = fmaxf(a0, a1);
    if (v2) m = fmaxf(m, a2);
#pragma unroll
    for (int off = 16; off > 0; off >>= 1)
        m = fmaxf(m, __shfl_xor_sync(0xffffffffu, m, off));
    float e0 = expf(a0 - m);
    float e1 = expf(a1 - m);
    float e2 = v2 ? expf(a2 - m) : 0.f;
    float ss = e0 + e1 + e2;
#pragma unroll
    for (int off = 16; off > 0; off >>= 1)
        ss += __shfl_xor_sync(0xffffffffu, ss, off);
    float inv = 1.f / ss;
    out[(size_t)v * NC + c0] = e0 * inv;
    out[(size_t)v * NC + c1] = e1 * inv;
    if (v2) out[(size_t)v * NC + c2] = e2 * inv;
}

// ---------------- launch ---------------------------------------------------------
extern "C" void kernel_launch(void* const* d_in, const int* in_sizes, int n_in,
                              void* d_out, int out_size) {
    const float* x     = (const float*)d_in[0];
    const int*   edges = (const int*)d_in[1];
    const float* W1    = (const float*)d_in[2];
    const float* b1    = (const float*)d_in[3];
    const float* W2    = (const float*)d_in[4];
    const float* b2    = (const float*)d_in[5];
    const int* src = edges;
    const int* dst = edges + NE;
    float* out = (float*)d_out;

    // one-time host-side setup (no device allocation; streams/events are host objs)
    static cudaStream_t s_side = 0;
    static cudaEvent_t  ev_fork = 0, ev_join = 0;
    static int inited = 0;
    if (!inited) {
        cudaStreamCreateWithFlags(&s_side, cudaStreamNonBlocking);
        cudaEventCreateWithFlags(&ev_fork, cudaEventDisableTiming);
        cudaEventCreateWithFlags(&ev_join, cudaEventDisableTiming);
        cudaFuncSetAttribute(k_gemm1_mma, cudaFuncAttributeMaxDynamicSharedMemorySize, SMTOT);
        inited = 1;
    }

    // fork: CSR build chain runs concurrently with convW + GEMM1
    cudaEventRecord(ev_fork, 0);
    cudaStreamWaitEvent(s_side, ev_fork, 0);

    k_init_deg<<<(NN + 255) / 256, 256, 0, s_side>>>();
    k_count  <<<(NE + 255) / 256, 256, 0, s_side>>>(dst);
    k_dinv   <<<(NN + 255) / 256, 256, 0, s_side>>>();
    k_scan   <<<1, 1024, 0, s_side>>>();
    k_fill   <<<(NE + 255) / 256, 256, 0, s_side>>>(src, dst);
    k_sort   <<<(NN + 255) / 256, 256, 0, s_side>>>();
    cudaEventRecord(ev_join, s_side);

    // main stream: dense path
    k_convW  <<<(HID * WSTR + 255) / 256, 256>>>(W1);
    k_gemm1_mma<<<GRID1, 320, SMTOT>>>(x);

    // join: aggregation needs both H1 and CSR
    cudaStreamWaitEvent(0, ev_join, 0);

    k_agg1   <<<(NN * 32 + 255) / 256, 256>>>(b1);
    k_gemm2  <<<NN / 8, 256>>>(W2);
    k_agg2   <<<(NN * 32 + 255) / 256, 256>>>(b2, out);
}

// round 15
// speedup vs baseline: 4.3057x; 1.0958x over previous
#include <cuda_runtime.h>
#include <cuda_fp16.h>
#include <stdint.h>

#define NN   20000
#define FIN  8710
#define HID  128
#define NC   70
#define NE   640000

#define KB    32                    // fp16 K per chunk
#define NCHK  273                   // ceil(8710/32)
#define WSTR  (NCHK * KB)           // 8736 padded K for W array

// GEMM1 tiling
#define BM    160                   // rows per CTA -> grid = 125 exactly
#define GRID1 (NN / BM)             // 125
#define AROW  80                    // smem row stride bytes (64B data + 16B pad)
#define ASZ   (BM * AROW)           // 12800
#define BSZ   (HID * AROW)          // 10240
#define STG   (ASZ + BSZ)           // 23040 per stage (A, B)
#define SMTOT (2 * STG)             // 46080

// ---------------- scratch (static device globals; no runtime alloc) -------------
__device__ float d_H1[NN * HID];
__device__ float d_G1[NN * HID];
__device__ float d_H2[NN * NC];
__device__ int   d_deg[NN];
__device__ float d_dinv[NN];
__device__ int   d_rowptr[NN + 1];
__device__ int   d_pos[NN];
__device__ int   d_col[NE];
__device__ __half d_Wf[HID * WSTR];          // [n][k] K-major transposed W1 (fp16)

// ================= helpers =======================================================
__device__ __forceinline__ uint32_t smem_u32(const void* p) {
    uint32_t a;
    asm("{ .reg .u64 t; cvta.to.shared.u64 t, %1; cvt.u32.u64 %0, t; }"
        : "=r"(a) : "l"(p));
    return a;
}
__device__ __forceinline__ void ldm_x4(uint32_t addr, uint32_t& r0, uint32_t& r1,
                                       uint32_t& r2, uint32_t& r3) {
    asm volatile("ldmatrix.sync.aligned.m8n8.x4.shared.b16 {%0,%1,%2,%3}, [%4];"
                 : "=r"(r0), "=r"(r1), "=r"(r2), "=r"(r3) : "r"(addr));
}
__device__ __forceinline__ void mma_f16(float* c, const uint32_t* a, const uint32_t* b) {
    asm volatile("mma.sync.aligned.m16n8k16.row.col.f32.f16.f16.f32 "
                 "{%0,%1,%2,%3}, {%4,%5,%6,%7}, {%8,%9}, {%0,%1,%2,%3};"
                 : "+f"(c[0]), "+f"(c[1]), "+f"(c[2]), "+f"(c[3])
                 : "r"(a[0]), "r"(a[1]), "r"(a[2]), "r"(a[3]),
                   "r"(b[0]), "r"(b[1]));
}
__device__ __forceinline__ uint32_t pack_h2(float2 v) {
    __half2 hp;
    hp.x = __float2half_rn(v.x);
    hp.y = __float2half_rn(v.y);
    return *(uint32_t*)&hp;
}

// ---------------- degree / CSR build --------------------------------------------
__global__ void k_init_deg() {
    int i = blockIdx.x * blockDim.x + threadIdx.x;
    if (i < NN) d_deg[i] = 1;
}
__global__ void k_count(const int* __restrict__ dst) {
    int e = blockIdx.x * blockDim.x + threadIdx.x;
    if (e < NE) atomicAdd(&d_deg[dst[e]], 1);
}
__global__ void k_dinv() {
    int i = blockIdx.x * blockDim.x + threadIdx.x;
    if (i < NN) d_dinv[i] = rsqrtf((float)d_deg[i]);
}
__global__ void k_scan() {
    __shared__ int sm[1024];
    __shared__ int carry;
    int t = threadIdx.x;
    if (t == 0) carry = 0;
    __syncthreads();
    for (int base = 0; base < NN; base += 1024) {
        int i = base + t;
        int v = (i < NN) ? (d_deg[i] - 1) : 0;
        sm[t] = v;
        __syncthreads();
        for (int off = 1; off < 1024; off <<= 1) {
            int a = (t >= off) ? sm[t - off] : 0;
            __syncthreads();
            sm[t] += a;
            __syncthreads();
        }
        if (i < NN) {
            int ex = carry + sm[t] - v;
            d_rowptr[i] = ex;
            d_pos[i]    = ex;
        }
        __syncthreads();
        if (t == 1023) carry += sm[1023];
        __syncthreads();
    }
    if (t == 0) d_rowptr[NN] = carry;
}
__global__ void k_fill(const int* __restrict__ src, const int* __restrict__ dst) {
    int e = blockIdx.x * blockDim.x + threadIdx.x;
    if (e < NE) {
        int d    = dst[e];
        int slot = atomicAdd(&d_pos[d], 1);
        d_col[slot] = src[e];
    }
}
__global__ void k_sort() {
    int v = blockIdx.x * blockDim.x + threadIdx.x;
    if (v >= NN) return;
    int b = d_rowptr[v], e = d_rowptr[v + 1];
    for (int i = b + 1; i < e; i++) {
        int key = d_col[i];
        int j = i - 1;
        while (j >= b && d_col[j] > key) { d_col[j + 1] = d_col[j]; j--; }
        d_col[j + 1] = key;
    }
}

// ---------------- W1 convert + transpose: d_Wf[n][k] (fp16) ----------------------
__global__ void k_convW(const float* __restrict__ W1) {
    int i = blockIdx.x * blockDim.x + threadIdx.x;   // over HID*WSTR, n-fast
    if (i >= HID * WSTR) return;
    int n = i & (HID - 1);
    int k = i >> 7;
    float v = (k < FIN) ? W1[k * HID + n] : 0.0f;
    d_Wf[(size_t)n * WSTR + k] = __float2half_rn(v);
}

// ---------------- GEMM1 via mma.sync fp16 single-term ----------------------------
// H1[20000,128] = X @ W1. CTA: 160x128, 320 thr (10 warps = 5m x 2n, warp 32x64).
// A fp16 (converted in-register), B fp16. fp32 accumulate.
// smem stage layout: A[160x80B] B[128x80B], double buffered.
__global__ void __launch_bounds__(320, 1) k_gemm1_mma(const float* __restrict__ X) {
    extern __shared__ char sm_[];
    const uint32_t sb = smem_u32(sm_);
    const int tid  = threadIdx.x;
    const int lane = tid & 31;
    const int wid  = tid >> 5;
    const int wm   = wid >> 1;          // 0..4
    const int wn   = wid & 1;           // 0..1
    const int bm   = blockIdx.x * BM;

    // fill mapping
    const int ar  = tid >> 1;                 // 0..159 A row
    const int aks = (tid & 1) << 4;           // 0/16 (elements)
    const float* xp = X + (size_t)(bm + ar) * FIN + aks;
    const int  bn  = tid >> 1;                // 0..127 (tid<256)
    const int  bks = (tid & 1) << 4;
    const bool bv  = tid < 256;
    const __half* wfp = d_Wf + (size_t)(bv ? bn : 0) * WSTR + bks;

    // ldmatrix per-lane offsets
    const int a_r     = lane & 15;
    const int a_kbyte = (lane >> 4) << 4;               // 0/16
    const uint32_t a_off = (uint32_t)((wm * 32 + a_r) * AROW + a_kbyte);
    const int b_r     = (lane & 7) + (((lane >> 4) & 1) << 3);
    const int b_kbyte = ((lane >> 3) & 1) << 4;         // 0/16
    const uint32_t b_off = (uint32_t)((wn * 64 + b_r) * AROW + b_kbyte);

    float acc[2][8][4];
#pragma unroll
    for (int mt = 0; mt < 2; mt++)
#pragma unroll
        for (int nt = 0; nt < 8; nt++)
#pragma unroll
            for (int q = 0; q < 4; q++) acc[mt][nt][q] = 0.f;

    float2 rA[8];
    uint4  rBf[2];

    auto ldgA = [&](int c) {
        const float* p = xp + c * KB;
        int kb = c * KB + aks;
#pragma unroll
        for (int j = 0; j < 8; j++)
            rA[j] = (kb + 2 * j < FIN) ? __ldg((const float2*)(p + 2 * j))
                                       : make_float2(0.f, 0.f);
    };
    auto ldgB = [&](int c) {
        if (bv) {
            rBf[0] = *(const uint4*)(wfp + c * KB);
            rBf[1] = *(const uint4*)(wfp + c * KB + 8);
        }
    };
    auto sts = [&](int s) {
        char* p = sm_ + s * STG;
        uint32_t hh[8];
#pragma unroll
        for (int j = 0; j < 8; j++) hh[j] = pack_h2(rA[j]);
        uint32_t ao = (uint32_t)(ar * AROW + aks * 2);
        *(uint4*)(p + ao)      = make_uint4(hh[0], hh[1], hh[2], hh[3]);
        *(uint4*)(p + ao + 16) = make_uint4(hh[4], hh[5], hh[6], hh[7]);
        if (bv) {
            uint32_t bo = (uint32_t)(bn * AROW + bks * 2);
            *(uint4*)(p + ASZ + bo)      = rBf[0];
            *(uint4*)(p + ASZ + bo + 16) = rBf[1];
        }
    };
    auto compute = [&](int s) {
        const uint32_t aA = sb + s * STG + a_off;
        const uint32_t bB = sb + s * STG + ASZ + b_off;
#pragma unroll
        for (int ks = 0; ks < 2; ks++) {
            uint32_t ah[2][4], bh[8][2];
#pragma unroll
            for (int mt = 0; mt < 2; mt++) {
                ldm_x4(aA + mt * (16 * AROW) + ks * 32,
                       ah[mt][0], ah[mt][1], ah[mt][2], ah[mt][3]);
            }
#pragma unroll
            for (int bt = 0; bt < 4; bt++) {
                ldm_x4(bB + bt * (16 * AROW) + ks * 32,
                       bh[2 * bt][0], bh[2 * bt][1], bh[2 * bt + 1][0], bh[2 * bt + 1][1]);
            }
#pragma unroll
            for (int mt = 0; mt < 2; mt++)
#pragma unroll
                for (int nt = 0; nt < 8; nt++)
                    mma_f16(acc[mt][nt], ah[mt], bh[nt]);
        }
    };

    // prologue
    ldgA(0); ldgB(0); sts(0);
    __syncthreads();

    for (int c = 0; c < NCHK; ++c) {
        const int s = c & 1;
        if (c + 1 < NCHK) { ldgA(c + 1); ldgB(c + 1); }
        compute(s);
        if (c + 1 < NCHK) sts(s ^ 1);
        __syncthreads();
    }

    // epilogue: acc frag -> global (lane: row = l/4 (+8), col = (l%4)*2 (+1))
#pragma unroll
    for (int mt = 0; mt < 2; mt++)
#pragma unroll
        for (int nt = 0; nt < 8; nt++) {
            int row = bm + wm * 32 + mt * 16 + (lane >> 2);
            int col = wn * 64 + nt * 8 + (lane & 3) * 2;
            *(float2*)&d_H1[(size_t)row * HID + col] =
                make_float2(acc[mt][nt][0], acc[mt][nt][1]);
            *(float2*)&d_H1[(size_t)(row + 8) * HID + col] =
                make_float2(acc[mt][nt][2], acc[mt][nt][3]);
        }
}

// ---------------- aggregation 1: G1 = relu(Â H1 + b1), warp per node ------------
__global__ void k_agg1(const float* __restrict__ b1) {
    int gw   = (blockIdx.x * blockDim.x + threadIdx.x) >> 5;
    int lane = threadIdx.x & 31;
    if (gw >= NN) return;
    int v = gw;
    float dv = d_dinv[v];
    float w0 = dv * dv;
    float4 h = *(const float4*)&d_H1[(size_t)v * HID + lane * 4];
    float ax = h.x * w0, ay = h.y * w0, az = h.z * w0, aw = h.w * w0;
    int b = d_rowptr[v], e = d_rowptr[v + 1];
    for (int i = b; i < e; i++) {
        int s = d_col[i];
        float wi = d_dinv[s] * dv;
        float4 hs = *(const float4*)&d_H1[(size_t)s * HID + lane * 4];
        ax = fmaf(wi, hs.x, ax);
        ay = fmaf(wi, hs.y, ay);
        az = fmaf(wi, hs.z, az);
        aw = fmaf(wi, hs.w, aw);
    }
    float4 bb = *(const float4*)&b1[lane * 4];
    ax = fmaxf(ax + bb.x, 0.f);
    ay = fmaxf(ay + bb.y, 0.f);
    az = fmaxf(az + bb.z, 0.f);
    aw = fmaxf(aw + bb.w, 0.f);
    *(float4*)&d_G1[(size_t)v * HID + lane * 4] = make_float4(ax, ay, az, aw);
}

// ---------------- GEMM2: H2[20000,70] = G1[20000,128] @ W2[128,70] --------------
__global__ void __launch_bounds__(256) k_gemm2(const float* __restrict__ W2) {
    __shared__ float W2s[HID * 72];
    __shared__ float srow[8][HID];
    int t = threadIdx.x;
    for (int i = t; i < HID * NC; i += 256) {
        int k = i / NC, c = i - k * NC;
        W2s[k * 72 + c] = W2[i];
    }
    __syncthreads();
    int w = t >> 5, lane = t & 31;
    int row = blockIdx.x * 8 + w;
    *(float4*)&srow[w][lane * 4] = *(const float4*)&d_G1[(size_t)row * HID + lane * 4];
    __syncwarp();
    float a0 = 0.f, a1 = 0.f, a2 = 0.f;
    int c0 = lane, c1 = lane + 32, c2 = lane + 64;
    bool v2 = (c2 < NC);
#pragma unroll 16
    for (int k = 0; k < HID; k++) {
        float x = srow[w][k];
        a0 = fmaf(x, W2s[k * 72 + c0], a0);
        a1 = fmaf(x, W2s[k * 72 + c1], a1);
        if (v2) a2 = fmaf(x, W2s[k * 72 + c2], a2);
    }
    d_H2[(size_t)row * NC + c0] = a0;
    d_H2[(size_t)row * NC + c1] = a1;
    if (v2) d_H2[(size_t)row * NC + c2] = a2;
}

// ---------------- aggregation 2 + bias + softmax, warp per node -----------------
__global__ void k_agg2(const float* __restrict__ b2, float* __restrict__ out) {
    int gw   = (blockIdx.x * blockDim.x + threadIdx.x) >> 5;
    int lane = threadIdx.x & 31;
    if (gw >= NN) return;
    int v = gw;
    float dv = d_dinv[v];
    float w0 = dv * dv;
    int c0 = lane, c1 = lane + 32, c2 = lane + 64;
    bool v2 = (c2 < NC);
    const float* H = d_H2;
    float a0 = H[(size_t)v * NC + c0] * w0;
    float a1 = H[(size_t)v * NC + c1] * w0;
    float a2 = v2 ? H[(size_t)v * NC + c2] * w0 : 0.f;
    int b = d_rowptr[v], e = d_rowptr[v + 1];
    for (int i = b; i < e; i++) {
        int s = d_col[i];
        float wi = d_dinv[s] * dv;
        size_t o = (size_t)s * NC;
        a0 = fmaf(wi, H[o + c0], a0);
        a1 = fmaf(wi, H[o + c1], a1);
        if (v2) a2 = fmaf(wi, H[o + c2], a2);
    }
    a0 += b2[c0];
    a1 += b2[c1];
    if (v2) a2 += b2[c2];

    float m = fmaxf(a0, a1);
    if (v2) m = fmaxf(m, a2);
#pragma unroll
    for (int off = 16; off > 0; off >>= 1)
        m = fmaxf(m, __shfl_xor_sync(0xffffffffu, m, off));
    float e0 = expf(a0 - m);
    float e1 = expf(a1 - m);
    float e2 = v2 ? expf(a2 - m) : 0.f;
    float ss = e0 + e1 + e2;
#pragma unroll
    for (int off = 16; off > 0; off >>= 1)
        ss += __shfl_xor_sync(0xffffffffu, ss, off);
    float inv = 1.f / ss;
    out[(size_t)v * NC + c0] = e0 * inv;
    out[(size_t)v * NC + c1] = e1 * inv;
    if (v2) out[(size_t)v * NC + c2] = e2 * inv;
}

// ---------------- launch ---------------------------------------------------------
extern "C" void kernel_launch(void* const* d_in, const int* in_sizes, int n_in,
                              void* d_out, int out_size) {
    const float* x     = (const float*)d_in[0];
    const int*   edges = (const int*)d_in[1];
    const float* W1    = (const float*)d_in[2];
    const float* b1    = (const float*)d_in[3];
    const float* W2    = (const float*)d_in[4];
    const float* b2    = (const float*)d_in[5];
    const int* src = edges;
    const int* dst = edges + NE;
    float* out = (float*)d_out;

    // one-time host-side setup (no device allocation; streams/events are host objs)
    static cudaStream_t s_side = 0;
    static cudaEvent_t  ev_fork = 0, ev_join = 0;
    static int inited = 0;
    if (!inited) {
        cudaStreamCreateWithFlags(&s_side, cudaStreamNonBlocking);
        cudaEventCreateWithFlags(&ev_fork, cudaEventDisableTiming);
        cudaEventCreateWithFlags(&ev_join, cudaEventDisableTiming);
        cudaFuncSetAttribute(k_gemm1_mma, cudaFuncAttributeMaxDynamicSharedMemorySize, SMTOT);
        inited = 1;
    }

    // fork: CSR build chain runs concurrently with convW + GEMM1
    cudaEventRecord(ev_fork, 0);
    cudaStreamWaitEvent(s_side, ev_fork, 0);

    k_init_deg<<<(NN + 255) / 256, 256, 0, s_side>>>();
    k_count  <<<(NE + 255) / 256, 256, 0, s_side>>>(dst);
    k_dinv   <<<(NN + 255) / 256, 256, 0, s_side>>>();
    k_scan   <<<1, 1024, 0, s_side>>>();
    k_fill   <<<(NE + 255) / 256, 256, 0, s_side>>>(src, dst);
    k_sort   <<<(NN + 255) / 256, 256, 0, s_side>>>();
    cudaEventRecord(ev_join, s_side);

    // main stream: dense path
    k_convW  <<<(HID * WSTR + 255) / 256, 256>>>(W1);
    k_gemm1_mma<<<GRID1, 320, SMTOT>>>(x);

    // join: aggregation needs both H1 and CSR
    cudaStreamWaitEvent(0, ev_join, 0);

    k_agg1   <<<(NN * 32 + 255) / 256, 256>>>(b1);
    k_gemm2  <<<NN / 8, 256>>>(W2);
    k_agg2   <<<(NN * 32 + 255) / 256, 256>>>(b2, out);
}

// round 16
// speedup vs baseline: 4.3079x; 1.0005x over previous
#include <cuda_runtime.h>
#include <cuda_fp16.h>
#include <stdint.h>

#define NN   20000
#define FIN  8710
#define HID  128
#define NC   70
#define NE   640000

#define KB    32                    // fp16 K per chunk
#define NCHK  273                   // ceil(8710/32)
#define WSTR  (NCHK * KB)           // 8736 padded K for W array

// GEMM1 tiling
#define BM    160                   // rows per CTA -> grid = 125 exactly
#define GRID1 (NN / BM)             // 125
#define AROW  80                    // smem row stride bytes (64B data + 16B pad)
#define ASZ   (BM * AROW)           // 12800
#define BSZ   (HID * AROW)          // 10240
#define STG   (ASZ + BSZ)           // 23040 per stage (A, B)
#define SMTOT (2 * STG)             // 46080

// ---------------- scratch (static device globals; no runtime alloc) -------------
__device__ float d_H1[NN * HID];
__device__ float d_G1[NN * HID];
__device__ float d_H2[NN * NC];
__device__ int   d_deg[NN];
__device__ float d_dinv[NN];
__device__ int   d_rowptr[NN + 1];
__device__ int   d_pos[NN];
__device__ int   d_col[NE];
__device__ __half d_Wf[HID * WSTR];          // [n][k] K-major transposed W1 (fp16)

// ================= helpers =======================================================
__device__ __forceinline__ uint32_t smem_u32(const void* p) {
    uint32_t a;
    asm("{ .reg .u64 t; cvta.to.shared.u64 t, %1; cvt.u32.u64 %0, t; }"
        : "=r"(a) : "l"(p));
    return a;
}
__device__ __forceinline__ void ldm_x4(uint32_t addr, uint32_t& r0, uint32_t& r1,
                                       uint32_t& r2, uint32_t& r3) {
    asm volatile("ldmatrix.sync.aligned.m8n8.x4.shared.b16 {%0,%1,%2,%3}, [%4];"
                 : "=r"(r0), "=r"(r1), "=r"(r2), "=r"(r3) : "r"(addr));
}
__device__ __forceinline__ void mma_f16(float* c, const uint32_t* a, const uint32_t* b) {
    asm volatile("mma.sync.aligned.m16n8k16.row.col.f32.f16.f16.f32 "
                 "{%0,%1,%2,%3}, {%4,%5,%6,%7}, {%8,%9}, {%0,%1,%2,%3};"
                 : "+f"(c[0]), "+f"(c[1]), "+f"(c[2]), "+f"(c[3])
                 : "r"(a[0]), "r"(a[1]), "r"(a[2]), "r"(a[3]),
                   "r"(b[0]), "r"(b[1]));
}
__device__ __forceinline__ uint32_t pack_h2(float2 v) {
    __half2 hp;
    hp.x = __float2half_rn(v.x);
    hp.y = __float2half_rn(v.y);
    return *(uint32_t*)&hp;
}

// ---------------- degree / CSR build --------------------------------------------
__global__ void k_init_deg() {
    int i = blockIdx.x * blockDim.x + threadIdx.x;
    if (i < NN) d_deg[i] = 1;
}
__global__ void k_count(const int* __restrict__ dst) {
    int e = blockIdx.x * blockDim.x + threadIdx.x;
    if (e < NE) atomicAdd(&d_deg[dst[e]], 1);
}
__global__ void k_dinv() {
    int i = blockIdx.x * blockDim.x + threadIdx.x;
    if (i < NN) d_dinv[i] = rsqrtf((float)d_deg[i]);
}
__global__ void k_scan() {
    __shared__ int sm[1024];
    __shared__ int carry;
    int t = threadIdx.x;
    if (t == 0) carry = 0;
    __syncthreads();
    for (int base = 0; base < NN; base += 1024) {
        int i = base + t;
        int v = (i < NN) ? (d_deg[i] - 1) : 0;
        sm[t] = v;
        __syncthreads();
        for (int off = 1; off < 1024; off <<= 1) {
            int a = (t >= off) ? sm[t - off] : 0;
            __syncthreads();
            sm[t] += a;
            __syncthreads();
        }
        if (i < NN) {
            int ex = carry + sm[t] - v;
            d_rowptr[i] = ex;
            d_pos[i]    = ex;
        }
        __syncthreads();
        if (t == 1023) carry += sm[1023];
        __syncthreads();
    }
    if (t == 0) d_rowptr[NN] = carry;
}
__global__ void k_fill(const int* __restrict__ src, const int* __restrict__ dst) {
    int e = blockIdx.x * blockDim.x + threadIdx.x;
    if (e < NE) {
        int d    = dst[e];
        int slot = atomicAdd(&d_pos[d], 1);
        d_col[slot] = src[e];
    }
}
__global__ void k_sort() {
    int v = blockIdx.x * blockDim.x + threadIdx.x;
    if (v >= NN) return;
    int b = d_rowptr[v], e = d_rowptr[v + 1];
    for (int i = b + 1; i < e; i++) {
        int key = d_col[i];
        int j = i - 1;
        while (j >= b && d_col[j] > key) { d_col[j + 1] = d_col[j]; j--; }
        d_col[j + 1] = key;
    }
}

// ---------------- W1 convert + transpose: d_Wf[n][k] (fp16) ----------------------
__global__ void k_convW(const float* __restrict__ W1) {
    int i = blockIdx.x * blockDim.x + threadIdx.x;   // over HID*WSTR, n-fast
    if (i >= HID * WSTR) return;
    int n = i & (HID - 1);
    int k = i >> 7;
    float v = (k < FIN) ? W1[k * HID + n] : 0.0f;
    d_Wf[(size_t)n * WSTR + k] = __float2half_rn(v);
}

// ---------------- GEMM1 via mma.sync fp16 single-term ----------------------------
// H1[20000,128] = X @ W1. CTA: 160x128, 320 thr (10 warps = 5m x 2n, warp 32x64).
// A fp16 (converted in-register), B fp16. fp32 accumulate.
// smem stage layout: A[160x80B] B[128x80B], double buffered.
__global__ void __launch_bounds__(320, 1) k_gemm1_mma(const float* __restrict__ X) {
    extern __shared__ char sm_[];
    const uint32_t sb = smem_u32(sm_);
    const int tid  = threadIdx.x;
    const int lane = tid & 31;
    const int wid  = tid >> 5;
    const int wm   = wid >> 1;          // 0..4
    const int wn   = wid & 1;           // 0..1
    const int bm   = blockIdx.x * BM;

    // fill mapping
    const int ar  = tid >> 1;                 // 0..159 A row
    const int aks = (tid & 1) << 4;           // 0/16 (elements)
    const float* xp = X + (size_t)(bm + ar) * FIN + aks;
    const int  bn  = tid >> 1;                // 0..127 (tid<256)
    const int  bks = (tid & 1) << 4;
    const bool bv  = tid < 256;
    const __half* wfp = d_Wf + (size_t)(bv ? bn : 0) * WSTR + bks;

    // ldmatrix per-lane offsets
    const int a_r     = lane & 15;
    const int a_kbyte = (lane >> 4) << 4;               // 0/16
    const uint32_t a_off = (uint32_t)((wm * 32 + a_r) * AROW + a_kbyte);
    const int b_r     = (lane & 7) + (((lane >> 4) & 1) << 3);
    const int b_kbyte = ((lane >> 3) & 1) << 4;         // 0/16
    const uint32_t b_off = (uint32_t)((wn * 64 + b_r) * AROW + b_kbyte);

    float acc[2][8][4];
#pragma unroll
    for (int mt = 0; mt < 2; mt++)
#pragma unroll
        for (int nt = 0; nt < 8; nt++)
#pragma unroll
            for (int q = 0; q < 4; q++) acc[mt][nt][q] = 0.f;

    float2 rA[8];
    uint4  rBf[2];

    auto ldgA = [&](int c) {
        const float* p = xp + c * KB;
        int kb = c * KB + aks;
#pragma unroll
        for (int j = 0; j < 8; j++)
            rA[j] = (kb + 2 * j < FIN) ? __ldg((const float2*)(p + 2 * j))
                                       : make_float2(0.f, 0.f);
    };
    auto ldgB = [&](int c) {
        if (bv) {
            rBf[0] = *(const uint4*)(wfp + c * KB);
            rBf[1] = *(const uint4*)(wfp + c * KB + 8);
        }
    };
    auto sts = [&](int s) {
        char* p = sm_ + s * STG;
        uint32_t hh[8];
#pragma unroll
        for (int j = 0; j < 8; j++) hh[j] = pack_h2(rA[j]);
        uint32_t ao = (uint32_t)(ar * AROW + aks * 2);
        *(uint4*)(p + ao)      = make_uint4(hh[0], hh[1], hh[2], hh[3]);
        *(uint4*)(p + ao + 16) = make_uint4(hh[4], hh[5], hh[6], hh[7]);
        if (bv) {
            uint32_t bo = (uint32_t)(bn * AROW + bks * 2);
            *(uint4*)(p + ASZ + bo)      = rBf[0];
            *(uint4*)(p + ASZ + bo + 16) = rBf[1];
        }
    };
    auto compute = [&](int s) {
        const uint32_t aA = sb + s * STG + a_off;
        const uint32_t bB = sb + s * STG + ASZ + b_off;
#pragma unroll
        for (int ks = 0; ks < 2; ks++) {
            uint32_t ah[2][4], bh[8][2];
#pragma unroll
            for (int mt = 0; mt < 2; mt++) {
                ldm_x4(aA + mt * (16 * AROW) + ks * 32,
                       ah[mt][0], ah[mt][1], ah[mt][2], ah[mt][3]);
            }
#pragma unroll
            for (int bt = 0; bt < 4; bt++) {
                ldm_x4(bB + bt * (16 * AROW) + ks * 32,
                       bh[2 * bt][0], bh[2 * bt][1], bh[2 * bt + 1][0], bh[2 * bt + 1][1]);
            }
#pragma unroll
            for (int mt = 0; mt < 2; mt++)
#pragma unroll
                for (int nt = 0; nt < 8; nt++)
                    mma_f16(acc[mt][nt], ah[mt], bh[nt]);
        }
    };

    // prologue
    ldgA(0); ldgB(0); sts(0);
    __syncthreads();

    for (int c = 0; c < NCHK; ++c) {
        const int s = c & 1;
        if (c + 1 < NCHK) { ldgA(c + 1); ldgB(c + 1); }
        compute(s);
        if (c + 1 < NCHK) sts(s ^ 1);
        __syncthreads();
    }

    // epilogue: acc frag -> global (lane: row = l/4 (+8), col = (l%4)*2 (+1))
#pragma unroll
    for (int mt = 0; mt < 2; mt++)
#pragma unroll
        for (int nt = 0; nt < 8; nt++) {
            int row = bm + wm * 32 + mt * 16 + (lane >> 2);
            int col = wn * 64 + nt * 8 + (lane & 3) * 2;
            *(float2*)&d_H1[(size_t)row * HID + col] =
                make_float2(acc[mt][nt][0], acc[mt][nt][1]);
            *(float2*)&d_H1[(size_t)(row + 8) * HID + col] =
                make_float2(acc[mt][nt][2], acc[mt][nt][3]);
        }
}

// ---------------- aggregation 1: G1 = relu(Â H1 + b1), warp per node ------------
__global__ void k_agg1(const float* __restrict__ b1) {
    int gw   = (blockIdx.x * blockDim.x + threadIdx.x) >> 5;
    int lane = threadIdx.x & 31;
    if (gw >= NN) return;
    int v = gw;
    float dv = d_dinv[v];
    float w0 = dv * dv;
    float4 h = *(const float4*)&d_H1[(size_t)v * HID + lane * 4];
    float ax = h.x * w0, ay = h.y * w0, az = h.z * w0, aw = h.w * w0;
    int b = d_rowptr[v], e = d_rowptr[v + 1];
    for (int i = b; i < e; i++) {
        int s = d_col[i];
        float wi = d_dinv[s] * dv;
        float4 hs = *(const float4*)&d_H1[(size_t)s * HID + lane * 4];
        ax = fmaf(wi, hs.x, ax);
        ay = fmaf(wi, hs.y, ay);
        az = fmaf(wi, hs.z, az);
        aw = fmaf(wi, hs.w, aw);
    }
    float4 bb = *(const float4*)&b1[lane * 4];
    ax = fmaxf(ax + bb.x, 0.f);
    ay = fmaxf(ay + bb.y, 0.f);
    az = fmaxf(az + bb.z, 0.f);
    aw = fmaxf(aw + bb.w, 0.f);
    *(float4*)&d_G1[(size_t)v * HID + lane * 4] = make_float4(ax, ay, az, aw);
}

// ---------------- GEMM2: H2[20000,70] = G1[20000,128] @ W2[128,70] --------------
__global__ void __launch_bounds__(256) k_gemm2(const float* __restrict__ W2) {
    __shared__ float W2s[HID * 72];
    __shared__ float srow[8][HID];
    int t = threadIdx.x;
    for (int i = t; i < HID * NC; i += 256) {
        int k = i / NC, c = i - k * NC;
        W2s[k * 72 + c] = W2[i];
    }
    __syncthreads();
    int w = t >> 5, lane = t & 31;
    int row = blockIdx.x * 8 + w;
    *(float4*)&srow[w][lane * 4] = *(const float4*)&d_G1[(size_t)row * HID + lane * 4];
    __syncwarp();
    float a0 = 0.f, a1 = 0.f, a2 = 0.f;
    int c0 = lane, c1 = lane + 32, c2 = lane + 64;
    bool v2 = (c2 < NC);
#pragma unroll 16
    for (int k = 0; k < HID; k++) {
        float x = srow[w][k];
        a0 = fmaf(x, W2s[k * 72 + c0], a0);
        a1 = fmaf(x, W2s[k * 72 + c1], a1);
        if (v2) a2 = fmaf(x, W2s[k * 72 + c2], a2);
    }
    d_H2[(size_t)row * NC + c0] = a0;
    d_H2[(size_t)row * NC + c1] = a1;
    if (v2) d_H2[(size_t)row * NC + c2] = a2;
}

// ---------------- aggregation 2 + bias + softmax, warp per node -----------------
__global__ void k_agg2(const float* __restrict__ b2, float* __restrict__ out) {
    int gw   = (blockIdx.x * blockDim.x + threadIdx.x) >> 5;
    int lane = threadIdx.x & 31;
    if (gw >= NN) return;
    int v = gw;
    float dv = d_dinv[v];
    float w0 = dv * dv;
    int c0 = lane, c1 = lane + 32, c2 = lane + 64;
    bool v2 = (c2 < NC);
    const float* H = d_H2;
    float a0 = H[(size_t)v * NC + c0] * w0;
    float a1 = H[(size_t)v * NC + c1] * w0;
    float a2 = v2 ? H[(size_t)v * NC + c2] * w0 : 0.f;
    int b = d_rowptr[v], e = d_rowptr[v + 1];
    for (int i = b; i < e; i++) {
        int s = d_col[i];
        float wi = d_dinv[s] * dv;
        size_t o = (size_t)s * NC;
        a0 = fmaf(wi, H[o + c0], a0);
        a1 = fmaf(wi, H[o + c1], a1);
        if (v2) a2 = fmaf(wi, H[o + c2], a2);
    }
    a0 += b2[c0];
    a1 += b2[c1];
    if (v2) a2 += b2[c2];

    float m = fmaxf(a0, a1);
    if (v2) m = fmaxf(m, a2);
#pragma unroll
    for (int off = 16; off > 0; off >>= 1)
        m = fmaxf(m, __shfl_xor_sync(0xffffffffu, m, off));
    float e0 = expf(a0 - m);
    float e1 = expf(a1 - m);
    float e2 = v2 ? expf(a2 - m) : 0.f;
    float ss = e0 + e1 + e2;
#pragma unroll
    for (int off = 16; off > 0; off >>= 1)
        ss += __shfl_xor_sync(0xffffffffu, ss, off);
    float inv = 1.f / ss;
    out[(size_t)v * NC + c0] = e0 * inv;
    out[(size_t)v * NC + c1] = e1 * inv;
    if (v2) out[(size_t)v * NC + c2] = e2 * inv;
}

// ---------------- launch ---------------------------------------------------------
extern "C" void kernel_launch(void* const* d_in, const int* in_sizes, int n_in,
                              void* d_out, int out_size) {
    const float* x     = (const float*)d_in[0];
    const int*   edges = (const int*)d_in[1];
    const float* W1    = (const float*)d_in[2];
    const float* b1    = (const float*)d_in[3];
    const float* W2    = (const float*)d_in[4];
    const float* b2    = (const float*)d_in[5];
    const int* src = edges;
    const int* dst = edges + NE;
    float* out = (float*)d_out;

    // one-time host-side setup (no device allocation; streams/events are host objs)
    static cudaStream_t s_side = 0;
    static cudaEvent_t  ev_fork = 0, ev_join = 0;
    static int inited = 0;
    if (!inited) {
        cudaStreamCreateWithFlags(&s_side, cudaStreamNonBlocking);
        cudaEventCreateWithFlags(&ev_fork, cudaEventDisableTiming);
        cudaEventCreateWithFlags(&ev_join, cudaEventDisableTiming);
        cudaFuncSetAttribute(k_gemm1_mma, cudaFuncAttributeMaxDynamicSharedMemorySize, SMTOT);
        inited = 1;
    }

    // fork: CSR build chain runs concurrently with convW + GEMM1
    cudaEventRecord(ev_fork, 0);
    cudaStreamWaitEvent(s_side, ev_fork, 0);

    k_init_deg<<<(NN + 255) / 256, 256, 0, s_side>>>();
    k_count  <<<(NE + 255) / 256, 256, 0, s_side>>>(dst);
    k_dinv   <<<(NN + 255) / 256, 256, 0, s_side>>>();
    k_scan   <<<1, 1024, 0, s_side>>>();
    k_fill   <<<(NE + 255) / 256, 256, 0, s_side>>>(src, dst);
    k_sort   <<<(NN + 255) / 256, 256, 0, s_side>>>();
    cudaEventRecord(ev_join, s_side);

    // main stream: dense path
    k_convW  <<<(HID * WSTR + 255) / 256, 256>>>(W1);
    k_gemm1_mma<<<GRID1, 320, SMTOT>>>(x);

    // join: aggregation needs both H1 and CSR
    cudaStreamWaitEvent(0, ev_join, 0);

    k_agg1   <<<(NN * 32 + 255) / 256, 256>>>(b1);
    k_gemm2  <<<NN / 8, 256>>>(W2);
    k_agg2   <<<(NN * 32 + 255) / 256, 256>>>(b2, out);
}

// round 17
// speedup vs baseline: 4.3082x; 1.0001x over previous
#include <cuda_runtime.h>
#include <cuda_fp16.h>
#include <stdint.h>

#define NN   20000
#define FIN  8710
#define HID  128
#define NC   70
#define NE   640000

#define KB    32                    // fp16 K per chunk
#define NCHK  273                   // ceil(8710/32)
#define WSTR  (NCHK * KB)           // 8736 padded K for W array

// GEMM1 tiling
#define BM    160                   // rows per CTA -> grid = 125 exactly
#define GRID1 (NN / BM)             // 125
#define AROW  80                    // smem row stride bytes (64B data + 16B pad)
#define ASZ   (BM * AROW)           // 12800
#define BSZ   (HID * AROW)          // 10240
#define STG   (ASZ + BSZ)           // 23040 per stage (A, B)
#define SMTOT (2 * STG)             // 46080

// ---------------- scratch (static device globals; no runtime alloc) -------------
__device__ float d_H1[NN * HID];
__device__ float d_G1[NN * HID];
__device__ float d_H2[NN * NC];
__device__ int   d_deg[NN];
__device__ float d_dinv[NN];
__device__ int   d_rowptr[NN + 1];
__device__ int   d_pos[NN];
__device__ int   d_col[NE];
__device__ __half d_Wf[HID * WSTR];          // [n][k] K-major transposed W1 (fp16)

// ================= helpers =======================================================
__device__ __forceinline__ uint32_t smem_u32(const void* p) {
    uint32_t a;
    asm("{ .reg .u64 t; cvta.to.shared.u64 t, %1; cvt.u32.u64 %0, t; }"
        : "=r"(a) : "l"(p));
    return a;
}
__device__ __forceinline__ void ldm_x4(uint32_t addr, uint32_t& r0, uint32_t& r1,
                                       uint32_t& r2, uint32_t& r3) {
    asm volatile("ldmatrix.sync.aligned.m8n8.x4.shared.b16 {%0,%1,%2,%3}, [%4];"
                 : "=r"(r0), "=r"(r1), "=r"(r2), "=r"(r3) : "r"(addr));
}
__device__ __forceinline__ void mma_f16(float* c, const uint32_t* a, const uint32_t* b) {
    asm volatile("mma.sync.aligned.m16n8k16.row.col.f32.f16.f16.f32 "
                 "{%0,%1,%2,%3}, {%4,%5,%6,%7}, {%8,%9}, {%0,%1,%2,%3};"
                 : "+f"(c[0]), "+f"(c[1]), "+f"(c[2]), "+f"(c[3])
                 : "r"(a[0]), "r"(a[1]), "r"(a[2]), "r"(a[3]),
                   "r"(b[0]), "r"(b[1]));
}
__device__ __forceinline__ uint32_t pack_h2(float2 v) {
    __half2 hp;
    hp.x = __float2half_rn(v.x);
    hp.y = __float2half_rn(v.y);
    return *(uint32_t*)&hp;
}

// ---------------- degree / CSR build --------------------------------------------
__global__ void k_init_deg() {
    int i = blockIdx.x * blockDim.x + threadIdx.x;
    if (i < NN) d_deg[i] = 1;
}
__global__ void k_count(const int* __restrict__ dst) {
    int e = blockIdx.x * blockDim.x + threadIdx.x;
    if (e < NE) atomicAdd(&d_deg[dst[e]], 1);
}
__global__ void k_dinv() {
    int i = blockIdx.x * blockDim.x + threadIdx.x;
    if (i < NN) d_dinv[i] = rsqrtf((float)d_deg[i]);
}
__global__ void k_scan() {
    __shared__ int sm[1024];
    __shared__ int carry;
    int t = threadIdx.x;
    if (t == 0) carry = 0;
    __syncthreads();
    for (int base = 0; base < NN; base += 1024) {
        int i = base + t;
        int v = (i < NN) ? (d_deg[i] - 1) : 0;
        sm[t] = v;
        __syncthreads();
        for (int off = 1; off < 1024; off <<= 1) {
            int a = (t >= off) ? sm[t - off] : 0;
            __syncthreads();
            sm[t] += a;
            __syncthreads();
        }
        if (i < NN) {
            int ex = carry + sm[t] - v;
            d_rowptr[i] = ex;
            d_pos[i]    = ex;
        }
        __syncthreads();
        if (t == 1023) carry += sm[1023];
        __syncthreads();
    }
    if (t == 0) d_rowptr[NN] = carry;
}
__global__ void k_fill(const int* __restrict__ src, const int* __restrict__ dst) {
    int e = blockIdx.x * blockDim.x + threadIdx.x;
    if (e < NE) {
        int d    = dst[e];
        int slot = atomicAdd(&d_pos[d], 1);
        d_col[slot] = src[e];
    }
}
__global__ void k_sort() {
    int v = blockIdx.x * blockDim.x + threadIdx.x;
    if (v >= NN) return;
    int b = d_rowptr[v], e = d_rowptr[v + 1];
    for (int i = b + 1; i < e; i++) {
        int key = d_col[i];
        int j = i - 1;
        while (j >= b && d_col[j] > key) { d_col[j + 1] = d_col[j]; j--; }
        d_col[j + 1] = key;
    }
}

// ---------------- W1 convert + transpose: d_Wf[n][k] (fp16) ----------------------
__global__ void k_convW(const float* __restrict__ W1) {
    int i = blockIdx.x * blockDim.x + threadIdx.x;   // over HID*WSTR, n-fast
    if (i >= HID * WSTR) return;
    int n = i & (HID - 1);
    int k = i >> 7;
    float v = (k < FIN) ? W1[k * HID + n] : 0.0f;
    d_Wf[(size_t)n * WSTR + k] = __float2half_rn(v);
}

// ---------------- GEMM1 via mma.sync fp16 single-term ----------------------------
// H1[20000,128] = X @ W1. CTA: 160x128, 320 thr (10 warps = 5m x 2n, warp 32x64).
// A fp16 (converted in-register), B fp16. fp32 accumulate.
// smem stage layout: A[160x80B] B[128x80B], double buffered.
__global__ void __launch_bounds__(320, 1) k_gemm1_mma(const float* __restrict__ X) {
    extern __shared__ char sm_[];
    const uint32_t sb = smem_u32(sm_);
    const int tid  = threadIdx.x;
    const int lane = tid & 31;
    const int wid  = tid >> 5;
    const int wm   = wid >> 1;          // 0..4
    const int wn   = wid & 1;           // 0..1
    const int bm   = blockIdx.x * BM;

    // fill mapping
    const int ar  = tid >> 1;                 // 0..159 A row
    const int aks = (tid & 1) << 4;           // 0/16 (elements)
    const float* xp = X + (size_t)(bm + ar) * FIN + aks;
    const int  bn  = tid >> 1;                // 0..127 (tid<256)
    const int  bks = (tid & 1) << 4;
    const bool bv  = tid < 256;
    const __half* wfp = d_Wf + (size_t)(bv ? bn : 0) * WSTR + bks;

    // ldmatrix per-lane offsets
    const int a_r     = lane & 15;
    const int a_kbyte = (lane >> 4) << 4;               // 0/16
    const uint32_t a_off = (uint32_t)((wm * 32 + a_r) * AROW + a_kbyte);
    const int b_r     = (lane & 7) + (((lane >> 4) & 1) << 3);
    const int b_kbyte = ((lane >> 3) & 1) << 4;         // 0/16
    const uint32_t b_off = (uint32_t)((wn * 64 + b_r) * AROW + b_kbyte);

    float acc[2][8][4];
#pragma unroll
    for (int mt = 0; mt < 2; mt++)
#pragma unroll
        for (int nt = 0; nt < 8; nt++)
#pragma unroll
            for (int q = 0; q < 4; q++) acc[mt][nt][q] = 0.f;

    float2 rA[8];
    uint4  rBf[2];

    auto ldgA = [&](int c) {
        const float* p = xp + c * KB;
        int kb = c * KB + aks;
#pragma unroll
        for (int j = 0; j < 8; j++)
            rA[j] = (kb + 2 * j < FIN) ? __ldg((const float2*)(p + 2 * j))
                                       : make_float2(0.f, 0.f);
    };
    auto ldgB = [&](int c) {
        if (bv) {
            rBf[0] = *(const uint4*)(wfp + c * KB);
            rBf[1] = *(const uint4*)(wfp + c * KB + 8);
        }
    };
    auto sts = [&](int s) {
        char* p = sm_ + s * STG;
        uint32_t hh[8];
#pragma unroll
        for (int j = 0; j < 8; j++) hh[j] = pack_h2(rA[j]);
        uint32_t ao = (uint32_t)(ar * AROW + aks * 2);
        *(uint4*)(p + ao)      = make_uint4(hh[0], hh[1], hh[2], hh[3]);
        *(uint4*)(p + ao + 16) = make_uint4(hh[4], hh[5], hh[6], hh[7]);
        if (bv) {
            uint32_t bo = (uint32_t)(bn * AROW + bks * 2);
            *(uint4*)(p + ASZ + bo)      = rBf[0];
            *(uint4*)(p + ASZ + bo + 16) = rBf[1];
        }
    };
    auto compute = [&](int s) {
        const uint32_t aA = sb + s * STG + a_off;
        const uint32_t bB = sb + s * STG + ASZ + b_off;
#pragma unroll
        for (int ks = 0; ks < 2; ks++) {
            uint32_t ah[2][4], bh[8][2];
#pragma unroll
            for (int mt = 0; mt < 2; mt++) {
                ldm_x4(aA + mt * (16 * AROW) + ks * 32,
                       ah[mt][0], ah[mt][1], ah[mt][2], ah[mt][3]);
            }
#pragma unroll
            for (int bt = 0; bt < 4; bt++) {
                ldm_x4(bB + bt * (16 * AROW) + ks * 32,
                       bh[2 * bt][0], bh[2 * bt][1], bh[2 * bt + 1][0], bh[2 * bt + 1][1]);
            }
#pragma unroll
            for (int mt = 0; mt < 2; mt++)
#pragma unroll
                for (int nt = 0; nt < 8; nt++)
                    mma_f16(acc[mt][nt], ah[mt], bh[nt]);
        }
    };

    // prologue
    ldgA(0); ldgB(0); sts(0);
    __syncthreads();

    for (int c = 0; c < NCHK; ++c) {
        const int s = c & 1;
        if (c + 1 < NCHK) { ldgA(c + 1); ldgB(c + 1); }
        compute(s);
        if (c + 1 < NCHK) sts(s ^ 1);
        __syncthreads();
    }

    // epilogue: acc frag -> global (lane: row = l/4 (+8), col = (l%4)*2 (+1))
#pragma unroll
    for (int mt = 0; mt < 2; mt++)
#pragma unroll
        for (int nt = 0; nt < 8; nt++) {
            int row = bm + wm * 32 + mt * 16 + (lane >> 2);
            int col = wn * 64 + nt * 8 + (lane & 3) * 2;
            *(float2*)&d_H1[(size_t)row * HID + col] =
                make_float2(acc[mt][nt][0], acc[mt][nt][1]);
            *(float2*)&d_H1[(size_t)(row + 8) * HID + col] =
                make_float2(acc[mt][nt][2], acc[mt][nt][3]);
        }
}

// ---------------- aggregation 1: G1 = relu(Â H1 + b1), warp per node ------------
__global__ void k_agg1(const float* __restrict__ b1) {
    int gw   = (blockIdx.x * blockDim.x + threadIdx.x) >> 5;
    int lane = threadIdx.x & 31;
    if (gw >= NN) return;
    int v = gw;
    float dv = d_dinv[v];
    float w0 = dv * dv;
    float4 h = *(const float4*)&d_H1[(size_t)v * HID + lane * 4];
    float ax = h.x * w0, ay = h.y * w0, az = h.z * w0, aw = h.w * w0;
    int b = d_rowptr[v], e = d_rowptr[v + 1];
    for (int i = b; i < e; i++) {
        int s = d_col[i];
        float wi = d_dinv[s] * dv;
        float4 hs = *(const float4*)&d_H1[(size_t)s * HID + lane * 4];
        ax = fmaf(wi, hs.x, ax);
        ay = fmaf(wi, hs.y, ay);
        az = fmaf(wi, hs.z, az);
        aw = fmaf(wi, hs.w, aw);
    }
    float4 bb = *(const float4*)&b1[lane * 4];
    ax = fmaxf(ax + bb.x, 0.f);
    ay = fmaxf(ay + bb.y, 0.f);
    az = fmaxf(az + bb.z, 0.f);
    aw = fmaxf(aw + bb.w, 0.f);
    *(float4*)&d_G1[(size_t)v * HID + lane * 4] = make_float4(ax, ay, az, aw);
}

// ---------------- GEMM2: H2[20000,70] = G1[20000,128] @ W2[128,70] --------------
__global__ void __launch_bounds__(256) k_gemm2(const float* __restrict__ W2) {
    __shared__ float W2s[HID * 72];
    __shared__ float srow[8][HID];
    int t = threadIdx.x;
    for (int i = t; i < HID * NC; i += 256) {
        int k = i / NC, c = i - k * NC;
        W2s[k * 72 + c] = W2[i];
    }
    __syncthreads();
    int w = t >> 5, lane = t & 31;
    int row = blockIdx.x * 8 + w;
    *(float4*)&srow[w][lane * 4] = *(const float4*)&d_G1[(size_t)row * HID + lane * 4];
    __syncwarp();
    float a0 = 0.f, a1 = 0.f, a2 = 0.f;
    int c0 = lane, c1 = lane + 32, c2 = lane + 64;
    bool v2 = (c2 < NC);
#pragma unroll 16
    for (int k = 0; k < HID; k++) {
        float x = srow[w][k];
        a0 = fmaf(x, W2s[k * 72 + c0], a0);
        a1 = fmaf(x, W2s[k * 72 + c1], a1);
        if (v2) a2 = fmaf(x, W2s[k * 72 + c2], a2);
    }
    d_H2[(size_t)row * NC + c0] = a0;
    d_H2[(size_t)row * NC + c1] = a1;
    if (v2) d_H2[(size_t)row * NC + c2] = a2;
}

// ---------------- aggregation 2 + bias + softmax, warp per node -----------------
__global__ void k_agg2(const float* __restrict__ b2, float* __restrict__ out) {
    int gw   = (blockIdx.x * blockDim.x + threadIdx.x) >> 5;
    int lane = threadIdx.x & 31;
    if (gw >= NN) return;
    int v = gw;
    float dv = d_dinv[v];
    float w0 = dv * dv;
    int c0 = lane, c1 = lane + 32, c2 = lane + 64;
    bool v2 = (c2 < NC);
    const float* H = d_H2;
    float a0 = H[(size_t)v * NC + c0] * w0;
    float a1 = H[(size_t)v * NC + c1] * w0;
    float a2 = v2 ? H[(size_t)v * NC + c2] * w0 : 0.f;
    int b = d_rowptr[v], e = d_rowptr[v + 1];
    for (int i = b; i < e; i++) {
        int s = d_col[i];
        float wi = d_dinv[s] * dv;
        size_t o = (size_t)s * NC;
        a0 = fmaf(wi, H[o + c0], a0);
        a1 = fmaf(wi, H[o + c1], a1);
        if (v2) a2 = fmaf(wi, H[o + c2], a2);
    }
    a0 += b2[c0];
    a1 += b2[c1];
    if (v2) a2 += b2[c2];

    float m = fmaxf(a0, a1);
    if (v2) m = fmaxf(m, a2);
#pragma unroll
    for (int off = 16; off > 0; off >>= 1)
        m = fmaxf(m, __shfl_xor_sync(0xffffffffu, m, off));
    float e0 = expf(a0 - m);
    float e1 = expf(a1 - m);
    float e2 = v2 ? expf(a2 - m) : 0.f;
    float ss = e0 + e1 + e2;
#pragma unroll
    for (int off = 16; off > 0; off >>= 1)
        ss += __shfl_xor_sync(0xffffffffu, ss, off);
    float inv = 1.f / ss;
    out[(size_t)v * NC + c0] = e0 * inv;
    out[(size_t)v * NC + c1] = e1 * inv;
    if (v2) out[(size_t)v * NC + c2] = e2 * inv;
}

// ---------------- launch ---------------------------------------------------------
extern "C" void kernel_launch(void* const* d_in, const int* in_sizes, int n_in,
                              void* d_out, int out_size) {
    const float* x     = (const float*)d_in[0];
    const int*   edges = (const int*)d_in[1];
    const float* W1    = (const float*)d_in[2];
    const float* b1    = (const float*)d_in[3];
    const float* W2    = (const float*)d_in[4];
    const float* b2    = (const float*)d_in[5];
    const int* src = edges;
    const int* dst = edges + NE;
    float* out = (float*)d_out;

    // one-time host-side setup (no device allocation; streams/events are host objs)
    static cudaStream_t s_side = 0;
    static cudaEvent_t  ev_fork = 0, ev_join = 0;
    static int inited = 0;
    if (!inited) {
        cudaStreamCreateWithFlags(&s_side, cudaStreamNonBlocking);
        cudaEventCreateWithFlags(&ev_fork, cudaEventDisableTiming);
        cudaEventCreateWithFlags(&ev_join, cudaEventDisableTiming);
        cudaFuncSetAttribute(k_gemm1_mma, cudaFuncAttributeMaxDynamicSharedMemorySize, SMTOT);
        inited = 1;
    }

    // fork: CSR build chain runs concurrently with convW + GEMM1
    cudaEventRecord(ev_fork, 0);
    cudaStreamWaitEvent(s_side, ev_fork, 0);

    k_init_deg<<<(NN + 255) / 256, 256, 0, s_side>>>();
    k_count  <<<(NE + 255) / 256, 256, 0, s_side>>>(dst);
    k_dinv   <<<(NN + 255) / 256, 256, 0, s_side>>>();
    k_scan   <<<1, 1024, 0, s_side>>>();
    k_fill   <<<(NE + 255) / 256, 256, 0, s_side>>>(src, dst);
    k_sort   <<<(NN + 255) / 256, 256, 0, s_side>>>();
    cudaEventRecord(ev_join, s_side);

    // main stream: dense path
    k_convW  <<<(HID * WSTR + 255) / 256, 256>>>(W1);
    k_gemm1_mma<<<GRID1, 320, SMTOT>>>(x);

    // join: aggregation needs both H1 and CSR
    cudaStreamWaitEvent(0, ev_join, 0);

    k_agg1   <<<(NN * 32 + 255) / 256, 256>>>(b1);
    k_gemm2  <<<NN / 8, 256>>>(W2);
    k_agg2   <<<(NN * 32 + 255) / 256, 256>>>(b2, out);
}